// round 1
// baseline (speedup 1.0000x reference)
#include <cuda_runtime.h>
#include <math.h>

#define BATCH 8
#define NN    2048
#define FF    256
#define OO    256
#define ROWS  (BATCH*NN)   /* 16384 */

#define BM 128
#define BN 128
#define BK 32

// ---------------- scratch (no allocations allowed) ----------------
__device__ float g_sin [ROWS];          // rsqrt(row sums)  (d_in)
__device__ float g_sout[ROWS];          // rsqrt(col sums)  (d_out)
__device__ float g_xn  [ROWS*FF];       // layernorm(x)
__device__ float g_xs  [ROWS*FF];       // s_in * xn
__device__ float g_z   [ROWS*FF];       // adj @ xs

// ---------------- helpers ----------------
__device__ __forceinline__ unsigned f2tf32(float x) {
    unsigned u;
    asm("cvt.rna.tf32.f32 %0, %1;" : "=r"(u) : "f"(x));
    return u;
}

__device__ __forceinline__ void mma_tf32(float (&d)[4], const unsigned (&a)[4], const unsigned (&b)[2]) {
    asm volatile(
        "mma.sync.aligned.m16n8k8.row.col.f32.tf32.tf32.f32 "
        "{%0,%1,%2,%3}, {%4,%5,%6,%7}, {%8,%9}, {%0,%1,%2,%3};\n"
        : "+f"(d[0]), "+f"(d[1]), "+f"(d[2]), "+f"(d[3])
        : "r"(a[0]), "r"(a[1]), "r"(a[2]), "r"(a[3]), "r"(b[0]), "r"(b[1]));
}

__device__ __forceinline__ float softplus_f(float x) {
    return fmaxf(x, 0.0f) + log1pf(expf(-fabsf(x)));
}

// ---------------- degree kernels ----------------
// row sums -> s_in
__global__ void rowsum_kernel(const float* __restrict__ adj) {
    int row = blockIdx.x;                         // 0..ROWS-1
    const float* p = adj + (size_t)row * NN;
    float s = 0.f;
    for (int j = threadIdx.x; j < NN; j += 256) s += p[j];
    __shared__ float red[256];
    red[threadIdx.x] = s;
    __syncthreads();
    for (int st = 128; st > 0; st >>= 1) {
        if (threadIdx.x < st) red[threadIdx.x] += red[threadIdx.x + st];
        __syncthreads();
    }
    if (threadIdx.x == 0) {
        float v = red[0];
        g_sin[row] = (v != 0.f) ? rsqrtf(v) : 0.f;
    }
}

// col sums -> s_out
__global__ void colsum_kernel(const float* __restrict__ adj) {
    int b = blockIdx.y;
    int j = blockIdx.x * 256 + threadIdx.x;       // column
    const float* p = adj + (size_t)b * NN * NN + j;
    float s = 0.f;
#pragma unroll 8
    for (int i = 0; i < NN; i++) s += p[(size_t)i * NN];
    g_sout[b * NN + j] = (s != 0.f) ? rsqrtf(s) : 0.f;
}

// ---------------- layernorm + s_in scaling ----------------
__global__ void ln_kernel(const float* __restrict__ x,
                          const float* __restrict__ gamma,
                          const float* __restrict__ beta) {
    int row  = blockIdx.x * 8 + (threadIdx.x >> 5);
    int lane = threadIdx.x & 31;
    const float4* px = (const float4*)(x + (size_t)row * FF);
    float4 v0 = px[lane];
    float4 v1 = px[lane + 32];

    float s  = v0.x + v0.y + v0.z + v0.w + v1.x + v1.y + v1.z + v1.w;
    float sq = v0.x*v0.x + v0.y*v0.y + v0.z*v0.z + v0.w*v0.w
             + v1.x*v1.x + v1.y*v1.y + v1.z*v1.z + v1.w*v1.w;
#pragma unroll
    for (int off = 16; off > 0; off >>= 1) {
        s  += __shfl_xor_sync(0xffffffffu, s,  off);
        sq += __shfl_xor_sync(0xffffffffu, sq, off);
    }
    float mu   = s * (1.0f / FF);
    float var  = sq * (1.0f / FF) - mu * mu;
    float rstd = rsqrtf(var + 1e-5f);
    float sinv = g_sin[row];

    const float4* pg = (const float4*)gamma;
    const float4* pb = (const float4*)beta;
    float4 g0 = pg[lane],      g1 = pg[lane + 32];
    float4 b0 = pb[lane],      b1 = pb[lane + 32];

    float4 xn0, xn1, xs0, xs1;
    xn0.x = (v0.x - mu) * rstd * g0.x + b0.x;  xs0.x = sinv * xn0.x;
    xn0.y = (v0.y - mu) * rstd * g0.y + b0.y;  xs0.y = sinv * xn0.y;
    xn0.z = (v0.z - mu) * rstd * g0.z + b0.z;  xs0.z = sinv * xn0.z;
    xn0.w = (v0.w - mu) * rstd * g0.w + b0.w;  xs0.w = sinv * xn0.w;
    xn1.x = (v1.x - mu) * rstd * g1.x + b1.x;  xs1.x = sinv * xn1.x;
    xn1.y = (v1.y - mu) * rstd * g1.y + b1.y;  xs1.y = sinv * xn1.y;
    xn1.z = (v1.z - mu) * rstd * g1.z + b1.z;  xs1.z = sinv * xn1.z;
    xn1.w = (v1.w - mu) * rstd * g1.w + b1.w;  xs1.w = sinv * xn1.w;

    float4* pxn = (float4*)(g_xn + (size_t)row * FF);
    float4* pxs = (float4*)(g_xs + (size_t)row * FF);
    pxn[lane] = xn0;  pxn[lane + 32] = xn1;
    pxs[lane] = xs0;  pxs[lane + 32] = xs1;
}

// ---------------- GEMM1: Z[b] = adj[b] @ xs[b]  (2048x2048 @ 2048x256, tf32) ----------------
__global__ void __launch_bounds__(256) gemm1_kernel(const float* __restrict__ adj) {
    __shared__ float As[BM][36];    // padded: bank-conflict-free fragment reads
    __shared__ float Bs[BK][132];

    int b  = blockIdx.z;
    int m0 = blockIdx.x * BM;
    int n0 = blockIdx.y * BN;

    const float* A  = adj  + (size_t)b * NN * NN;
    const float* Bm = g_xs + (size_t)b * NN * FF;
    float*       Z  = g_z  + (size_t)b * NN * FF;

    int tid  = threadIdx.x;
    int warp = tid >> 5, lane = tid & 31;
    int wm = warp >> 1, wn = warp & 1;      // 4 x 2 warp grid -> warp tile 32x64
    int g  = lane >> 2, tg = lane & 3;

    float acc[2][8][4];
#pragma unroll
    for (int i = 0; i < 2; i++)
#pragma unroll
        for (int j = 0; j < 8; j++)
#pragma unroll
            for (int k = 0; k < 4; k++) acc[i][j][k] = 0.f;

    for (int k0 = 0; k0 < NN; k0 += BK) {
        // stage A tile (128x32) with tf32 rounding
#pragma unroll
        for (int l = 0; l < 4; l++) {
            int idx  = tid + l * 256;
            int ar   = idx >> 3;
            int ac   = (idx & 7) * 4;
            float4 v = *(const float4*)&A[(size_t)(m0 + ar) * NN + k0 + ac];
            As[ar][ac + 0] = __uint_as_float(f2tf32(v.x));
            As[ar][ac + 1] = __uint_as_float(f2tf32(v.y));
            As[ar][ac + 2] = __uint_as_float(f2tf32(v.z));
            As[ar][ac + 3] = __uint_as_float(f2tf32(v.w));
        }
        // stage B tile (32x128)
#pragma unroll
        for (int l = 0; l < 4; l++) {
            int idx  = tid + l * 256;
            int br   = idx >> 5;
            int bc   = (idx & 31) * 4;
            float4 v = *(const float4*)&Bm[(size_t)(k0 + br) * FF + n0 + bc];
            Bs[br][bc + 0] = __uint_as_float(f2tf32(v.x));
            Bs[br][bc + 1] = __uint_as_float(f2tf32(v.y));
            Bs[br][bc + 2] = __uint_as_float(f2tf32(v.z));
            Bs[br][bc + 3] = __uint_as_float(f2tf32(v.w));
        }
        __syncthreads();

#pragma unroll
        for (int ks = 0; ks < BK / 8; ks++) {
            int kb = ks * 8;
            unsigned a[2][4], bb[8][2];
#pragma unroll
            for (int tm = 0; tm < 2; tm++) {
                int r = wm * 32 + tm * 16;
                a[tm][0] = __float_as_uint(As[r + g    ][kb + tg    ]);
                a[tm][1] = __float_as_uint(As[r + g + 8][kb + tg    ]);
                a[tm][2] = __float_as_uint(As[r + g    ][kb + tg + 4]);
                a[tm][3] = __float_as_uint(As[r + g + 8][kb + tg + 4]);
            }
#pragma unroll
            for (int nt = 0; nt < 8; nt++) {
                int c = wn * 64 + nt * 8 + g;
                bb[nt][0] = __float_as_uint(Bs[kb + tg    ][c]);
                bb[nt][1] = __float_as_uint(Bs[kb + tg + 4][c]);
            }
#pragma unroll
            for (int tm = 0; tm < 2; tm++)
#pragma unroll
                for (int nt = 0; nt < 8; nt++)
                    mma_tf32(acc[tm][nt], a[tm], bb[nt]);
        }
        __syncthreads();
    }

    // epilogue: write Z
#pragma unroll
    for (int tm = 0; tm < 2; tm++) {
#pragma unroll
        for (int nt = 0; nt < 8; nt++) {
            int r = m0 + wm * 32 + tm * 16 + g;
            int c = n0 + wn * 64 + nt * 8 + tg * 2;
            float2 v0 = make_float2(acc[tm][nt][0], acc[tm][nt][1]);
            float2 v1 = make_float2(acc[tm][nt][2], acc[tm][nt][3]);
            *(float2*)&Z[(size_t)r * FF + c]       = v0;
            *(float2*)&Z[(size_t)(r + 8) * FF + c] = v1;
        }
    }
}

// ---------------- GEMM2: out = softplus(xn @ (Ws+Wn) - (s_out*Z) @ Wn) ----------------
__global__ void __launch_bounds__(256) gemm2_kernel(const float* __restrict__ Wself,
                                                    const float* __restrict__ Wneigh,
                                                    float* __restrict__ out) {
    __shared__ float As[BM][36];
    __shared__ float Bs[BK][132];

    int m0 = blockIdx.x * BM;   // flattened B*N rows
    int n0 = blockIdx.y * BN;

    int tid  = threadIdx.x;
    int warp = tid >> 5, lane = tid & 31;
    int wm = warp >> 1, wn = warp & 1;
    int g  = lane >> 2, tg = lane & 3;

    float acc[2][8][4];
#pragma unroll
    for (int i = 0; i < 2; i++)
#pragma unroll
        for (int j = 0; j < 8; j++)
#pragma unroll
            for (int k = 0; k < 4; k++) acc[i][j][k] = 0.f;

    for (int k0 = 0; k0 < FF; k0 += BK) {
#pragma unroll
        for (int phase = 0; phase < 2; phase++) {
            // A tile
#pragma unroll
            for (int l = 0; l < 4; l++) {
                int idx = tid + l * 256;
                int ar  = idx >> 3;
                int ac  = (idx & 7) * 4;
                int grow = m0 + ar;
                float4 v;
                if (phase == 0) {
                    v = *(const float4*)&g_xn[(size_t)grow * FF + k0 + ac];
                } else {
                    v = *(const float4*)&g_z[(size_t)grow * FF + k0 + ac];
                    float sc = -g_sout[grow];
                    v.x *= sc; v.y *= sc; v.z *= sc; v.w *= sc;
                }
                As[ar][ac + 0] = __uint_as_float(f2tf32(v.x));
                As[ar][ac + 1] = __uint_as_float(f2tf32(v.y));
                As[ar][ac + 2] = __uint_as_float(f2tf32(v.z));
                As[ar][ac + 3] = __uint_as_float(f2tf32(v.w));
            }
            // B tile
#pragma unroll
            for (int l = 0; l < 4; l++) {
                int idx = tid + l * 256;
                int br  = idx >> 5;
                int bc  = (idx & 31) * 4;
                float4 w = *(const float4*)&Wneigh[(size_t)(k0 + br) * OO + n0 + bc];
                if (phase == 0) {
                    float4 ws = *(const float4*)&Wself[(size_t)(k0 + br) * OO + n0 + bc];
                    w.x += ws.x; w.y += ws.y; w.z += ws.z; w.w += ws.w;
                }
                Bs[br][bc + 0] = __uint_as_float(f2tf32(w.x));
                Bs[br][bc + 1] = __uint_as_float(f2tf32(w.y));
                Bs[br][bc + 2] = __uint_as_float(f2tf32(w.z));
                Bs[br][bc + 3] = __uint_as_float(f2tf32(w.w));
            }
            __syncthreads();

#pragma unroll
            for (int ks = 0; ks < BK / 8; ks++) {
                int kb = ks * 8;
                unsigned a[2][4], bb[8][2];
#pragma unroll
                for (int tm = 0; tm < 2; tm++) {
                    int r = wm * 32 + tm * 16;
                    a[tm][0] = __float_as_uint(As[r + g    ][kb + tg    ]);
                    a[tm][1] = __float_as_uint(As[r + g + 8][kb + tg    ]);
                    a[tm][2] = __float_as_uint(As[r + g    ][kb + tg + 4]);
                    a[tm][3] = __float_as_uint(As[r + g + 8][kb + tg + 4]);
                }
#pragma unroll
                for (int nt = 0; nt < 8; nt++) {
                    int c = wn * 64 + nt * 8 + g;
                    bb[nt][0] = __float_as_uint(Bs[kb + tg    ][c]);
                    bb[nt][1] = __float_as_uint(Bs[kb + tg + 4][c]);
                }
#pragma unroll
                for (int tm = 0; tm < 2; tm++)
#pragma unroll
                    for (int nt = 0; nt < 8; nt++)
                        mma_tf32(acc[tm][nt], a[tm], bb[nt]);
            }
            __syncthreads();
        }
    }

    // epilogue: softplus + store
#pragma unroll
    for (int tm = 0; tm < 2; tm++) {
#pragma unroll
        for (int nt = 0; nt < 8; nt++) {
            int r = m0 + wm * 32 + tm * 16 + g;
            int c = n0 + wn * 64 + nt * 8 + tg * 2;
            float2 v0 = make_float2(softplus_f(acc[tm][nt][0]), softplus_f(acc[tm][nt][1]));
            float2 v1 = make_float2(softplus_f(acc[tm][nt][2]), softplus_f(acc[tm][nt][3]));
            *(float2*)&out[(size_t)r * OO + c]       = v0;
            *(float2*)&out[(size_t)(r + 8) * OO + c] = v1;
        }
    }
}

// ---------------- launch ----------------
extern "C" void kernel_launch(void* const* d_in, const int* in_sizes, int n_in,
                              void* d_out, int out_size) {
    const float* x      = (const float*)d_in[0];
    const float* adj    = (const float*)d_in[1];
    const float* gamma  = (const float*)d_in[2];
    const float* beta   = (const float*)d_in[3];
    const float* Wself  = (const float*)d_in[4];
    const float* Wneigh = (const float*)d_in[5];
    float* out = (float*)d_out;

    rowsum_kernel<<<ROWS, 256>>>(adj);
    colsum_kernel<<<dim3(NN / 256, BATCH), 256>>>(adj);
    ln_kernel<<<ROWS / 8, 256>>>(x, gamma, beta);
    gemm1_kernel<<<dim3(NN / BM, FF / BN, BATCH), 256>>>(adj);
    gemm2_kernel<<<dim3(ROWS / BM, OO / BN), 256>>>(Wself, Wneigh, out);
}

// round 2
// speedup vs baseline: 2.1061x; 2.1061x over previous
#include <cuda_runtime.h>
#include <cstdint>
#include <math.h>

#define BATCH 8
#define NN    2048
#define FF    256
#define OO    256
#define ROWS  (BATCH*NN)   /* 16384 */

// GEMM tiling (both gemms): 128x256 CTA tile, K-step 32, 512 threads
#define BM 128
#define BN 256
#define BK 32
#define NTHREADS 512
#define APAD 36            /* A smem row stride (floats) */
#define BPAD 260           /* B smem row stride (floats) */
#define A_TILE (BM*APAD)   /* 4608 floats */
#define B_TILE (BK*BPAD)   /* 8320 floats */
#define SMEM_FLOATS (2*A_TILE + 2*B_TILE)
#define SMEM_BYTES  (SMEM_FLOATS*4)   /* 103424 B */

// ---------------- scratch ----------------
__device__ float g_rs  [ROWS];       // row sums of adj (d_in)
__device__ float g_cs  [ROWS];       // col sums of adj (d_out), atomically accumulated
__device__ float g_xn  [ROWS*FF];    // layernorm(x), tf32-rounded
__device__ float g_xs  [ROWS*FF];    // s_in * xn, tf32-rounded
__device__ float g_z   [ROWS*FF];    // -s_out * (adj @ xs), tf32-rounded
__device__ float g_wsum[FF*OO];      // tf32(Wself + Wneigh)
__device__ float g_wn  [FF*OO];      // tf32(Wneigh)

// ---------------- helpers ----------------
__device__ __forceinline__ unsigned f2tf32(float x) {
    unsigned u;
    asm("cvt.rna.tf32.f32 %0, %1;" : "=r"(u) : "f"(x));
    return u;
}

__device__ __forceinline__ void mma_tf32(float (&d)[4], const unsigned (&a)[4], const unsigned (&b)[2]) {
    asm volatile(
        "mma.sync.aligned.m16n8k8.row.col.f32.tf32.tf32.f32 "
        "{%0,%1,%2,%3}, {%4,%5,%6,%7}, {%8,%9}, {%0,%1,%2,%3};\n"
        : "+f"(d[0]), "+f"(d[1]), "+f"(d[2]), "+f"(d[3])
        : "r"(a[0]), "r"(a[1]), "r"(a[2]), "r"(a[3]), "r"(b[0]), "r"(b[1]));
}

__device__ __forceinline__ void cp16(uint32_t smem_dst, const void* gsrc) {
    asm volatile("cp.async.cg.shared.global [%0], [%1], 16;\n" :: "r"(smem_dst), "l"(gsrc));
}
#define CP_COMMIT()  asm volatile("cp.async.commit_group;\n" ::: "memory")
#define CP_WAIT1()   asm volatile("cp.async.wait_group 1;\n" ::: "memory")

__device__ __forceinline__ float softplus_f(float x) {
    return fmaxf(x, 0.0f) + log1pf(expf(-fabsf(x)));
}

// ---------------- tiny prep kernels ----------------
__global__ void zero_cs_kernel() {
    g_cs[blockIdx.x * 256 + threadIdx.x] = 0.f;
}

__global__ void wsum_kernel(const float* __restrict__ Ws, const float* __restrict__ Wn) {
    int i = blockIdx.x * 256 + threadIdx.x;
    g_wsum[i] = __uint_as_float(f2tf32(Ws[i] + Wn[i]));
    g_wn[i]   = __uint_as_float(f2tf32(Wn[i]));
}

// ---------------- fused degree kernel: ONE pass over adj ----------------
// block = 64 rows x 2048 cols. Row sums via shared reduce; col sums via global atomics.
__global__ void __launch_bounds__(256) degree_kernel(const float* __restrict__ adj) {
    __shared__ float rowpart[64][9];
    int tid = threadIdx.x, lane = tid & 31, w = tid >> 5;
    size_t r0 = (size_t)blockIdx.x * 64;
    const float* base = adj + r0 * NN;
    int c0 = tid * 4;

    float cs[8] = {0,0,0,0,0,0,0,0};
#pragma unroll 4
    for (int rr = 0; rr < 64; rr++) {
        float4 v0 = *(const float4*)(base + (size_t)rr * NN + c0);
        float4 v1 = *(const float4*)(base + (size_t)rr * NN + c0 + 1024);
        cs[0] += v0.x; cs[1] += v0.y; cs[2] += v0.z; cs[3] += v0.w;
        cs[4] += v1.x; cs[5] += v1.y; cs[6] += v1.z; cs[7] += v1.w;
        float rs = v0.x + v0.y + v0.z + v0.w + v1.x + v1.y + v1.z + v1.w;
#pragma unroll
        for (int off = 16; off > 0; off >>= 1) rs += __shfl_xor_sync(0xffffffffu, rs, off);
        if (lane == 0) rowpart[rr][w] = rs;
    }
    __syncthreads();
    if (tid < 64) {
        float s = 0.f;
#pragma unroll
        for (int j = 0; j < 8; j++) s += rowpart[tid][j];
        g_rs[r0 + tid] = s;
    }
    int b = (int)(r0 >> 11);
    float* cbase = g_cs + (size_t)b * NN;
#pragma unroll
    for (int j = 0; j < 4; j++) atomicAdd(cbase + c0 + j, cs[j]);
#pragma unroll
    for (int j = 0; j < 4; j++) atomicAdd(cbase + c0 + 1024 + j, cs[4 + j]);
}

// ---------------- layernorm (+ s_in scaling, tf32 pre-rounding) ----------------
__global__ void ln_kernel(const float* __restrict__ x,
                          const float* __restrict__ gamma,
                          const float* __restrict__ beta) {
    int row  = blockIdx.x * 8 + (threadIdx.x >> 5);
    int lane = threadIdx.x & 31;
    const float4* px = (const float4*)(x + (size_t)row * FF);
    float4 v0 = px[lane];
    float4 v1 = px[lane + 32];

    float s  = v0.x + v0.y + v0.z + v0.w + v1.x + v1.y + v1.z + v1.w;
    float sq = v0.x*v0.x + v0.y*v0.y + v0.z*v0.z + v0.w*v0.w
             + v1.x*v1.x + v1.y*v1.y + v1.z*v1.z + v1.w*v1.w;
#pragma unroll
    for (int off = 16; off > 0; off >>= 1) {
        s  += __shfl_xor_sync(0xffffffffu, s,  off);
        sq += __shfl_xor_sync(0xffffffffu, sq, off);
    }
    float mu   = s * (1.0f / FF);
    float var  = sq * (1.0f / FF) - mu * mu;
    float rstd = rsqrtf(var + 1e-5f);
    float din  = g_rs[row];
    float sinv = (din != 0.f) ? rsqrtf(din) : 0.f;

    const float4* pg = (const float4*)gamma;
    const float4* pb = (const float4*)beta;
    float4 g0 = pg[lane], g1 = pg[lane + 32];
    float4 b0 = pb[lane], b1 = pb[lane + 32];

    float xn[8], gm[8], bt[8], xv[8];
    xv[0]=v0.x; xv[1]=v0.y; xv[2]=v0.z; xv[3]=v0.w; xv[4]=v1.x; xv[5]=v1.y; xv[6]=v1.z; xv[7]=v1.w;
    gm[0]=g0.x; gm[1]=g0.y; gm[2]=g0.z; gm[3]=g0.w; gm[4]=g1.x; gm[5]=g1.y; gm[6]=g1.z; gm[7]=g1.w;
    bt[0]=b0.x; bt[1]=b0.y; bt[2]=b0.z; bt[3]=b0.w; bt[4]=b1.x; bt[5]=b1.y; bt[6]=b1.z; bt[7]=b1.w;

    float4 oxn[2], oxs[2];
    float* pxn = (float*)&oxn[0];
    float* pxs = (float*)&oxs[0];
#pragma unroll
    for (int j = 0; j < 8; j++) {
        xn[j]  = (xv[j] - mu) * rstd * gm[j] + bt[j];
        pxn[j] = __uint_as_float(f2tf32(xn[j]));
        pxs[j] = __uint_as_float(f2tf32(sinv * xn[j]));
    }
    float4* dxn = (float4*)(g_xn + (size_t)row * FF);
    float4* dxs = (float4*)(g_xs + (size_t)row * FF);
    dxn[lane] = oxn[0]; dxn[lane + 32] = oxn[1];
    dxs[lane] = oxs[0]; dxs[lane + 32] = oxs[1];
}

// ---------------- GEMM1: g_z[b] = -s_out * (adj[b] @ xs[b])  (tf32, cp.async x2 buf) ----------------
__global__ void __launch_bounds__(NTHREADS, 1) gemm1_kernel(const float* __restrict__ adj) {
    extern __shared__ float sm[];
    float* As = sm;              // [2][A_TILE]
    float* Bs = sm + 2 * A_TILE; // [2][B_TILE]

    int b  = blockIdx.z;
    int m0 = blockIdx.x * BM;
    const float* A  = adj  + (size_t)b * NN * NN;
    const float* Bm = g_xs + (size_t)b * NN * FF;

    int tid = threadIdx.x, warp = tid >> 5, lane = tid & 31;
    int wm = warp >> 2, wn = warp & 3;          // 4x4 warp grid, warp tile 32x64
    int g = lane >> 2, tg = lane & 3;

    float acc[2][8][4];
#pragma unroll
    for (int i = 0; i < 2; i++)
#pragma unroll
        for (int j = 0; j < 8; j++)
#pragma unroll
            for (int k = 0; k < 4; k++) acc[i][j][k] = 0.f;

    auto load_tiles = [&](int k0, int buf) {
        float* Ad = As + buf * A_TILE;
        float* Bd = Bs + buf * B_TILE;
#pragma unroll
        for (int l = 0; l < 2; l++) {
            int idx = tid + l * NTHREADS;
            int ar = idx >> 3, ac = (idx & 7) * 4;
            cp16((uint32_t)__cvta_generic_to_shared(Ad + ar * APAD + ac),
                 A + (size_t)(m0 + ar) * NN + k0 + ac);
        }
#pragma unroll
        for (int l = 0; l < 4; l++) {
            int idx = tid + l * NTHREADS;
            int br = idx >> 6, bc = (idx & 63) * 4;
            cp16((uint32_t)__cvta_generic_to_shared(Bd + br * BPAD + bc),
                 Bm + (size_t)(k0 + br) * FF + bc);
        }
    };

    load_tiles(0, 0);
    CP_COMMIT();

    const int KT = NN / BK;  // 64
    for (int kt = 0; kt < KT; kt++) {
        if (kt + 1 < KT) load_tiles((kt + 1) * BK, (kt + 1) & 1);
        CP_COMMIT();
        CP_WAIT1();
        __syncthreads();

        const float* Ab = As + (kt & 1) * A_TILE;
        const float* Bb = Bs + (kt & 1) * B_TILE;
#pragma unroll
        for (int ks = 0; ks < BK / 8; ks++) {
            int kb = ks * 8;
            unsigned a[2][4], bb[8][2];
#pragma unroll
            for (int tm = 0; tm < 2; tm++) {
                int r = wm * 32 + tm * 16;
                a[tm][0] = f2tf32(Ab[(r + g    ) * APAD + kb + tg    ]);
                a[tm][1] = f2tf32(Ab[(r + g + 8) * APAD + kb + tg    ]);
                a[tm][2] = f2tf32(Ab[(r + g    ) * APAD + kb + tg + 4]);
                a[tm][3] = f2tf32(Ab[(r + g + 8) * APAD + kb + tg + 4]);
            }
#pragma unroll
            for (int nt = 0; nt < 8; nt++) {
                int c = wn * 64 + nt * 8 + g;
                bb[nt][0] = __float_as_uint(Bb[(kb + tg    ) * BPAD + c]);
                bb[nt][1] = __float_as_uint(Bb[(kb + tg + 4) * BPAD + c]);
            }
#pragma unroll
            for (int tm = 0; tm < 2; tm++)
#pragma unroll
                for (int nt = 0; nt < 8; nt++)
                    mma_tf32(acc[tm][nt], a[tm], bb[nt]);
        }
        __syncthreads();
    }

    // epilogue: scale by -s_out (from raw col sums), tf32-round, store
    float* Z = g_z + (size_t)b * NN * FF;
    const float* cb = g_cs + (size_t)b * NN;
#pragma unroll
    for (int tm = 0; tm < 2; tm++) {
        int rl = m0 + wm * 32 + tm * 16 + g;
        float c0v = cb[rl],     c1v = cb[rl + 8];
        float sc0 = (c0v != 0.f) ? -rsqrtf(c0v) : 0.f;
        float sc1 = (c1v != 0.f) ? -rsqrtf(c1v) : 0.f;
#pragma unroll
        for (int nt = 0; nt < 8; nt++) {
            int c = wn * 64 + nt * 8 + tg * 2;
            float2 v0, v1;
            v0.x = __uint_as_float(f2tf32(acc[tm][nt][0] * sc0));
            v0.y = __uint_as_float(f2tf32(acc[tm][nt][1] * sc0));
            v1.x = __uint_as_float(f2tf32(acc[tm][nt][2] * sc1));
            v1.y = __uint_as_float(f2tf32(acc[tm][nt][3] * sc1));
            *(float2*)&Z[(size_t)rl * FF + c]       = v0;
            *(float2*)&Z[(size_t)(rl + 8) * FF + c] = v1;
        }
    }
}

// ---------------- GEMM2: out = softplus([xn | z] @ [Wsum ; Wn])  K=512 concat GEMM ----------------
__global__ void __launch_bounds__(NTHREADS, 1) gemm2_kernel(float* __restrict__ out) {
    extern __shared__ float sm[];
    float* As = sm;
    float* Bs = sm + 2 * A_TILE;

    int m0 = blockIdx.x * BM;   // flattened B*N rows
    int tid = threadIdx.x, warp = tid >> 5, lane = tid & 31;
    int wm = warp >> 2, wn = warp & 3;
    int g = lane >> 2, tg = lane & 3;

    float acc[2][8][4];
#pragma unroll
    for (int i = 0; i < 2; i++)
#pragma unroll
        for (int j = 0; j < 8; j++)
#pragma unroll
            for (int k = 0; k < 4; k++) acc[i][j][k] = 0.f;

    auto load_tiles = [&](int kk0, int buf) {
        const float* Asrc = (kk0 < FF) ? g_xn   : g_z;
        const float* Bsrc = (kk0 < FF) ? g_wsum : g_wn;
        int kc = (kk0 < FF) ? kk0 : (kk0 - FF);
        float* Ad = As + buf * A_TILE;
        float* Bd = Bs + buf * B_TILE;
#pragma unroll
        for (int l = 0; l < 2; l++) {
            int idx = tid + l * NTHREADS;
            int ar = idx >> 3, ac = (idx & 7) * 4;
            cp16((uint32_t)__cvta_generic_to_shared(Ad + ar * APAD + ac),
                 Asrc + (size_t)(m0 + ar) * FF + kc + ac);
        }
#pragma unroll
        for (int l = 0; l < 4; l++) {
            int idx = tid + l * NTHREADS;
            int br = idx >> 6, bc = (idx & 63) * 4;
            cp16((uint32_t)__cvta_generic_to_shared(Bd + br * BPAD + bc),
                 Bsrc + (size_t)(kc + br) * OO + bc);
        }
    };

    load_tiles(0, 0);
    CP_COMMIT();

    const int KT = (2 * FF) / BK;  // 16
    for (int kt = 0; kt < KT; kt++) {
        if (kt + 1 < KT) load_tiles((kt + 1) * BK, (kt + 1) & 1);
        CP_COMMIT();
        CP_WAIT1();
        __syncthreads();

        const float* Ab = As + (kt & 1) * A_TILE;
        const float* Bb = Bs + (kt & 1) * B_TILE;
#pragma unroll
        for (int ks = 0; ks < BK / 8; ks++) {
            int kb = ks * 8;
            unsigned a[2][4], bb[8][2];
#pragma unroll
            for (int tm = 0; tm < 2; tm++) {
                int r = wm * 32 + tm * 16;
                a[tm][0] = __float_as_uint(Ab[(r + g    ) * APAD + kb + tg    ]);
                a[tm][1] = __float_as_uint(Ab[(r + g + 8) * APAD + kb + tg    ]);
                a[tm][2] = __float_as_uint(Ab[(r + g    ) * APAD + kb + tg + 4]);
                a[tm][3] = __float_as_uint(Ab[(r + g + 8) * APAD + kb + tg + 4]);
            }
#pragma unroll
            for (int nt = 0; nt < 8; nt++) {
                int c = wn * 64 + nt * 8 + g;
                bb[nt][0] = __float_as_uint(Bb[(kb + tg    ) * BPAD + c]);
                bb[nt][1] = __float_as_uint(Bb[(kb + tg + 4) * BPAD + c]);
            }
#pragma unroll
            for (int tm = 0; tm < 2; tm++)
#pragma unroll
                for (int nt = 0; nt < 8; nt++)
                    mma_tf32(acc[tm][nt], a[tm], bb[nt]);
        }
        __syncthreads();
    }

    // epilogue: softplus + store
#pragma unroll
    for (int tm = 0; tm < 2; tm++) {
#pragma unroll
        for (int nt = 0; nt < 8; nt++) {
            int r = m0 + wm * 32 + tm * 16 + g;
            int c = wn * 64 + nt * 8 + tg * 2;
            float2 v0 = make_float2(softplus_f(acc[tm][nt][0]), softplus_f(acc[tm][nt][1]));
            float2 v1 = make_float2(softplus_f(acc[tm][nt][2]), softplus_f(acc[tm][nt][3]));
            *(float2*)&out[(size_t)r * OO + c]       = v0;
            *(float2*)&out[(size_t)(r + 8) * OO + c] = v1;
        }
    }
}

// ---------------- launch ----------------
extern "C" void kernel_launch(void* const* d_in, const int* in_sizes, int n_in,
                              void* d_out, int out_size) {
    const float* x      = (const float*)d_in[0];
    const float* adj    = (const float*)d_in[1];
    const float* gamma  = (const float*)d_in[2];
    const float* beta   = (const float*)d_in[3];
    const float* Wself  = (const float*)d_in[4];
    const float* Wneigh = (const float*)d_in[5];
    float* out = (float*)d_out;

    cudaFuncSetAttribute(gemm1_kernel, cudaFuncAttributeMaxDynamicSharedMemorySize, SMEM_BYTES);
    cudaFuncSetAttribute(gemm2_kernel, cudaFuncAttributeMaxDynamicSharedMemorySize, SMEM_BYTES);

    zero_cs_kernel<<<ROWS / 256, 256>>>();
    wsum_kernel<<<(FF * OO) / 256, 256>>>(Wself, Wneigh);
    degree_kernel<<<ROWS / 64, 256>>>(adj);
    ln_kernel<<<ROWS / 8, 256>>>(x, gamma, beta);
    gemm1_kernel<<<dim3(NN / BM, 1, BATCH), NTHREADS, SMEM_BYTES>>>(adj);
    gemm2_kernel<<<ROWS / BM, NTHREADS, SMEM_BYTES>>>(out);
}

// round 5
// speedup vs baseline: 2.8332x; 1.3453x over previous
#include <cuda_runtime.h>
#include <cuda_fp16.h>
#include <cstdint>
#include <math.h>

#define BATCH 8
#define NN    2048
#define FF    256
#define OO    256
#define ROWS  (BATCH*NN)   /* 16384 */

// GEMM tiling: 128x256 CTA tile, K-step 32, 512 threads, fp16 operands
#define BM 128
#define BN 256
#define BK 32
#define NTH 512
#define APADH 40                 /* halfs per A smem row */
#define BPADH 40                 /* halfs per B smem row */
#define A_TILE_H (BM*APADH)      /* 5120 halfs  = 10240 B */
#define B_TILE_H (BN*BPADH)      /* 10240 halfs = 20480 B */
#define NSTAGE 3
#define SMEM_BYTES (NSTAGE*(A_TILE_H+B_TILE_H)*2)   /* 92160 B */

// ---------------- scratch ----------------
__device__ float  g_rs  [ROWS];          // row sums of adj
__device__ float  g_cs  [ROWS];          // col sums of adj (atomic)
__device__ __half g_adjh[(size_t)BATCH*NN*NN];  // fp16 copy of adj (67 MB)
__device__ __half g_xnh [ROWS*FF];       // fp16 layernorm(x), row-major
__device__ __half g_xshT[ROWS*FF];       // fp16 transposed: [b][f][n] = s_in*xn
__device__ __half g_zh  [ROWS*FF];       // fp16 -s_out*(adj @ xs), row-major
__device__ __half g_wT  [2*FF*OO];       // [0]=(Ws+Wn)^T, [1]=Wn^T, both [o][k]

// ---------------- helpers ----------------
__device__ __forceinline__ uint32_t h2u(__half2 h) {
    return *reinterpret_cast<uint32_t*>(&h);
}
__device__ __forceinline__ float softplus_f(float x) {
    return fmaxf(x, 0.0f) + log1pf(expf(-fabsf(x)));
}
__device__ __forceinline__ void cp16(uint32_t dst, const void* src) {
    asm volatile("cp.async.cg.shared.global [%0], [%1], 16;\n" :: "r"(dst), "l"(src));
}
#define CP_COMMIT() asm volatile("cp.async.commit_group;\n" ::: "memory")
#define CP_WAIT(n)  asm volatile("cp.async.wait_group %0;\n" :: "n"(n) : "memory")

__device__ __forceinline__ void mma_f16(float (&d)[4], const uint32_t (&a)[4], const uint32_t (&b)[2]) {
    asm volatile(
        "mma.sync.aligned.m16n8k16.row.col.f32.f16.f16.f32 "
        "{%0,%1,%2,%3}, {%4,%5,%6,%7}, {%8,%9}, {%0,%1,%2,%3};\n"
        : "+f"(d[0]), "+f"(d[1]), "+f"(d[2]), "+f"(d[3])
        : "r"(a[0]), "r"(a[1]), "r"(a[2]), "r"(a[3]), "r"(b[0]), "r"(b[1]));
}

// ---------------- tiny prep kernels ----------------
__global__ void zero_cs_kernel() {
    g_cs[blockIdx.x * 256 + threadIdx.x] = 0.f;
}

// 32x32 tile transpose of Wsum and Wn into fp16 [o][k]
__global__ void __launch_bounds__(256) wtrans_kernel(const float* __restrict__ Ws,
                                                     const float* __restrict__ Wn) {
    __shared__ float t1[32][33], t2[32][33];
    int tx = threadIdx.x & 31, ty = threadIdx.x >> 5;   // 32 x 8
    int k0 = blockIdx.x * 32, o0 = blockIdx.y * 32;
#pragma unroll
    for (int i = 0; i < 4; i++) {
        int k = k0 + ty + i * 8;
        float wn = Wn[(size_t)k * OO + o0 + tx];
        float ws = Ws[(size_t)k * OO + o0 + tx];
        t1[ty + i * 8][tx] = ws + wn;
        t2[ty + i * 8][tx] = wn;
    }
    __syncthreads();
#pragma unroll
    for (int i = 0; i < 4; i++) {
        int o = o0 + ty + i * 8;
        g_wT[(size_t)o * FF + k0 + tx]            = __float2half_rn(t1[tx][ty + i * 8]);
        g_wT[FF * OO + (size_t)o * FF + k0 + tx]  = __float2half_rn(t2[tx][ty + i * 8]);
    }
}

// ---------------- fused degree + fp16-convert kernel: one adj pass ----------------
__global__ void __launch_bounds__(256) degree_kernel(const float* __restrict__ adj) {
    __shared__ float rowpart[64][9];
    int tid = threadIdx.x, lane = tid & 31, w = tid >> 5;
    size_t r0 = (size_t)blockIdx.x * 64;
    const float* base = adj + r0 * NN;
    int c0 = tid * 4;

    float cs[8] = {0,0,0,0,0,0,0,0};
#pragma unroll 4
    for (int rr = 0; rr < 64; rr++) {
        float4 v0 = *(const float4*)(base + (size_t)rr * NN + c0);
        float4 v1 = *(const float4*)(base + (size_t)rr * NN + c0 + 1024);
        // fp16 copy
        __half2 h0 = __floats2half2_rn(v0.x, v0.y);
        __half2 h1 = __floats2half2_rn(v0.z, v0.w);
        __half2 h2 = __floats2half2_rn(v1.x, v1.y);
        __half2 h3 = __floats2half2_rn(v1.z, v1.w);
        __half* hd = g_adjh + (r0 + rr) * NN;
        *(uint2*)(hd + c0)        = make_uint2(h2u(h0), h2u(h1));
        *(uint2*)(hd + c0 + 1024) = make_uint2(h2u(h2), h2u(h3));

        cs[0] += v0.x; cs[1] += v0.y; cs[2] += v0.z; cs[3] += v0.w;
        cs[4] += v1.x; cs[5] += v1.y; cs[6] += v1.z; cs[7] += v1.w;
        float rs = v0.x + v0.y + v0.z + v0.w + v1.x + v1.y + v1.z + v1.w;
#pragma unroll
        for (int off = 16; off > 0; off >>= 1) rs += __shfl_xor_sync(0xffffffffu, rs, off);
        if (lane == 0) rowpart[rr][w] = rs;
    }
    __syncthreads();
    if (tid < 64) {
        float s = 0.f;
#pragma unroll
        for (int j = 0; j < 8; j++) s += rowpart[tid][j];
        g_rs[r0 + tid] = s;
    }
    int b = (int)(r0 >> 11);
    float* cbase = g_cs + (size_t)b * NN;
#pragma unroll
    for (int j = 0; j < 4; j++) atomicAdd(cbase + c0 + j, cs[j]);
#pragma unroll
    for (int j = 0; j < 4; j++) atomicAdd(cbase + c0 + 1024 + j, cs[4 + j]);
}

// ---------------- layernorm + fp16 outputs (row-major xn, K-major xs^T) ----------------
__global__ void __launch_bounds__(256) ln_kernel(const float* __restrict__ x,
                                                 const float* __restrict__ gamma,
                                                 const float* __restrict__ beta) {
    __shared__ float tr[256 * 37];   // [feature][klocal]
    int tid = threadIdx.x, w = tid >> 5, lane = tid & 31;
    size_t r0 = (size_t)blockIdx.x * 32;
    int b  = (int)(r0 >> 11);
    int k0 = (int)(r0 & 2047);

    const float4* pg = (const float4*)gamma;
    const float4* pb = (const float4*)beta;
    float4 g0 = pg[lane], g1 = pg[lane + 32];
    float4 b0 = pb[lane], b1 = pb[lane + 32];

#pragma unroll
    for (int s = 0; s < 4; s++) {
        int kk = w * 4 + s;
        size_t row = r0 + kk;
        const float4* px = (const float4*)(x + row * FF);
        float4 v0 = px[lane], v1 = px[lane + 32];

        float sm = v0.x + v0.y + v0.z + v0.w + v1.x + v1.y + v1.z + v1.w;
        float sq = v0.x*v0.x + v0.y*v0.y + v0.z*v0.z + v0.w*v0.w
                 + v1.x*v1.x + v1.y*v1.y + v1.z*v1.z + v1.w*v1.w;
#pragma unroll
        for (int off = 16; off > 0; off >>= 1) {
            sm += __shfl_xor_sync(0xffffffffu, sm, off);
            sq += __shfl_xor_sync(0xffffffffu, sq, off);
        }
        float mu   = sm * (1.0f / FF);
        float var  = sq * (1.0f / FF) - mu * mu;
        float rstd = rsqrtf(var + 1e-5f);
        float din  = g_rs[row];
        float sinv = (din != 0.f) ? rsqrtf(din) : 0.f;

        float xv[8], gm[8], bt[8], xn[8];
        xv[0]=v0.x; xv[1]=v0.y; xv[2]=v0.z; xv[3]=v0.w; xv[4]=v1.x; xv[5]=v1.y; xv[6]=v1.z; xv[7]=v1.w;
        gm[0]=g0.x; gm[1]=g0.y; gm[2]=g0.z; gm[3]=g0.w; gm[4]=g1.x; gm[5]=g1.y; gm[6]=g1.z; gm[7]=g1.w;
        bt[0]=b0.x; bt[1]=b0.y; bt[2]=b0.z; bt[3]=b0.w; bt[4]=b1.x; bt[5]=b1.y; bt[6]=b1.z; bt[7]=b1.w;

#pragma unroll
        for (int j = 0; j < 8; j++) {
            xn[j] = (xv[j] - mu) * rstd * gm[j] + bt[j];
            int n = (j < 4) ? (lane * 4 + j) : (128 + lane * 4 + j - 4);
            tr[n * 37 + kk] = sinv * xn[j];
        }
        // fp16 xn row-major: elements [4*lane..4*lane+3] and [128+4*lane..+3]
        __half2 p0 = __floats2half2_rn(xn[0], xn[1]);
        __half2 p1 = __floats2half2_rn(xn[2], xn[3]);
        __half2 p2 = __floats2half2_rn(xn[4], xn[5]);
        __half2 p3 = __floats2half2_rn(xn[6], xn[7]);
        __half* dst = g_xnh + row * FF;
        *(uint2*)(dst + lane * 4)       = make_uint2(h2u(p0), h2u(p1));
        *(uint2*)(dst + 128 + lane * 4) = make_uint2(h2u(p2), h2u(p3));
    }
    __syncthreads();

    // transposed fp16 write: thread = feature, 32 contiguous node-k
    __half* dst = g_xshT + (size_t)b * FF * NN + (size_t)tid * NN + k0;
#pragma unroll
    for (int j = 0; j < 32; j += 8) {
        uint4 o;
        o.x = h2u(__floats2half2_rn(tr[tid*37 + j + 0], tr[tid*37 + j + 1]));
        o.y = h2u(__floats2half2_rn(tr[tid*37 + j + 2], tr[tid*37 + j + 3]));
        o.z = h2u(__floats2half2_rn(tr[tid*37 + j + 4], tr[tid*37 + j + 5]));
        o.w = h2u(__floats2half2_rn(tr[tid*37 + j + 6], tr[tid*37 + j + 7]));
        *(uint4*)(dst + j) = o;
    }
}

// ---------------- GEMM1 (fp16 mma): g_zh[b] = -s_out * (adj[b] @ xs[b]) ----------------
__global__ void __launch_bounds__(NTH, 1) gemm1_kernel() {
    extern __shared__ __half sh[];
    __half* sA = sh;                       // [NSTAGE][A_TILE_H]
    __half* sB = sh + NSTAGE * A_TILE_H;   // [NSTAGE][B_TILE_H]

    int b  = blockIdx.y;
    int m0 = blockIdx.x * BM;
    const __half* A  = g_adjh + (size_t)(b * NN + m0) * NN;
    const __half* Bt = g_xshT + (size_t)b * FF * NN;

    int tid = threadIdx.x, warp = tid >> 5, lane = tid & 31;
    int wm = warp >> 2, wn = warp & 3;       // 4x4 warps, warp tile 32x64
    int g = lane >> 2, tg = lane & 3;

    float acc[2][8][4];
#pragma unroll
    for (int i = 0; i < 2; i++)
#pragma unroll
        for (int j = 0; j < 8; j++)
#pragma unroll
            for (int k = 0; k < 4; k++) acc[i][j][k] = 0.f;

    auto load = [&](int kt, int buf) {
        int k0 = kt * BK;
        __half* Ad = sA + buf * A_TILE_H;
        __half* Bd = sB + buf * B_TILE_H;
        {   // A: 128 rows x 32 k = 512 chunks of 8 halfs, 1 per thread
            int ar = tid >> 2, ac8 = (tid & 3) * 8;
            cp16((uint32_t)__cvta_generic_to_shared(Ad + ar * APADH + ac8),
                 A + (size_t)ar * NN + k0 + ac8);
        }
#pragma unroll
        for (int l = 0; l < 2; l++) {   // B: 256 feats x 32 k = 1024 chunks
            int idx = tid + l * NTH;
            int br = idx >> 2, bc8 = (idx & 3) * 8;
            cp16((uint32_t)__cvta_generic_to_shared(Bd + br * BPADH + bc8),
                 Bt + (size_t)br * NN + k0 + bc8);
        }
    };

    const int KT = NN / BK;   // 64
    load(0, 0); CP_COMMIT();
    load(1, 1); CP_COMMIT();

    for (int kt = 0; kt < KT; kt++) {
        if (kt + 2 < KT) { load(kt + 2, (kt + 2) % NSTAGE); CP_COMMIT(); CP_WAIT(2); }
        else             { CP_WAIT(0); }
        __syncthreads();

        int buf = kt % NSTAGE;
        const __half* Ab = sA + buf * A_TILE_H;
        const __half* Bb = sB + buf * B_TILE_H;
#pragma unroll
        for (int ks = 0; ks < BK / 16; ks++) {
            int kk = ks * 16;
            uint32_t a[2][4], bb[8][2];
#pragma unroll
            for (int tm = 0; tm < 2; tm++) {
                int r = wm * 32 + tm * 16;
                a[tm][0] = *(const uint32_t*)(Ab + (r + g    ) * APADH + kk + 2*tg);
                a[tm][1] = *(const uint32_t*)(Ab + (r + g + 8) * APADH + kk + 2*tg);
                a[tm][2] = *(const uint32_t*)(Ab + (r + g    ) * APADH + kk + 8 + 2*tg);
                a[tm][3] = *(const uint32_t*)(Ab + (r + g + 8) * APADH + kk + 8 + 2*tg);
            }
#pragma unroll
            for (int nt = 0; nt < 8; nt++) {
                int c = wn * 64 + nt * 8 + g;
                bb[nt][0] = *(const uint32_t*)(Bb + c * BPADH + kk + 2*tg);
                bb[nt][1] = *(const uint32_t*)(Bb + c * BPADH + kk + 8 + 2*tg);
            }
#pragma unroll
            for (int tm = 0; tm < 2; tm++)
#pragma unroll
                for (int nt = 0; nt < 8; nt++)
                    mma_f16(acc[tm][nt], a[tm], bb[nt]);
        }
        __syncthreads();
    }

    // epilogue: scale by -s_out, fp16, store
    const float* cb = g_cs + (size_t)b * NN;
#pragma unroll
    for (int tm = 0; tm < 2; tm++) {
        int rl = m0 + wm * 32 + tm * 16 + g;
        float c0v = cb[rl], c1v = cb[rl + 8];
        float sc0 = (c0v != 0.f) ? -rsqrtf(c0v) : 0.f;
        float sc1 = (c1v != 0.f) ? -rsqrtf(c1v) : 0.f;
        __half* z0 = g_zh + ((size_t)b * NN + rl)     * FF;
        __half* z1 = g_zh + ((size_t)b * NN + rl + 8) * FF;
#pragma unroll
        for (int nt = 0; nt < 8; nt++) {
            int c = wn * 64 + nt * 8 + tg * 2;
            *(uint32_t*)(z0 + c) = h2u(__floats2half2_rn(acc[tm][nt][0]*sc0, acc[tm][nt][1]*sc0));
            *(uint32_t*)(z1 + c) = h2u(__floats2half2_rn(acc[tm][nt][2]*sc1, acc[tm][nt][3]*sc1));
        }
    }
}

// ---------------- GEMM2 (fp16 mma): out = softplus([xn|z] @ [Wsum;Wn]) ----------------
__global__ void __launch_bounds__(NTH, 1) gemm2_kernel(float* __restrict__ out) {
    extern __shared__ __half sh[];
    __half* sA = sh;
    __half* sB = sh + NSTAGE * A_TILE_H;

    int m0 = blockIdx.x * BM;
    int tid = threadIdx.x, warp = tid >> 5, lane = tid & 31;
    int wm = warp >> 2, wn = warp & 3;
    int g = lane >> 2, tg = lane & 3;

    float acc[2][8][4];
#pragma unroll
    for (int i = 0; i < 2; i++)
#pragma unroll
        for (int j = 0; j < 8; j++)
#pragma unroll
            for (int k = 0; k < 4; k++) acc[i][j][k] = 0.f;

    auto load = [&](int kt, int buf) {
        int kk0 = kt * BK;
        const __half* Asrc = (kk0 < FF) ? g_xnh : g_zh;
        const __half* Bsrc = g_wT + ((kk0 < FF) ? 0 : FF * OO);
        int kc = (kk0 < FF) ? kk0 : (kk0 - FF);
        __half* Ad = sA + buf * A_TILE_H;
        __half* Bd = sB + buf * B_TILE_H;
        {
            int ar = tid >> 2, ac8 = (tid & 3) * 8;
            cp16((uint32_t)__cvta_generic_to_shared(Ad + ar * APADH + ac8),
                 Asrc + (size_t)(m0 + ar) * FF + kc + ac8);
        }
#pragma unroll
        for (int l = 0; l < 2; l++) {
            int idx = tid + l * NTH;
            int br = idx >> 2, bc8 = (idx & 3) * 8;
            cp16((uint32_t)__cvta_generic_to_shared(Bd + br * BPADH + bc8),
                 Bsrc + (size_t)br * FF + kc + bc8);
        }
    };

    const int KT = (2 * FF) / BK;   // 16
    load(0, 0); CP_COMMIT();
    load(1, 1); CP_COMMIT();

    for (int kt = 0; kt < KT; kt++) {
        if (kt + 2 < KT) { load(kt + 2, (kt + 2) % NSTAGE); CP_COMMIT(); CP_WAIT(2); }
        else             { CP_WAIT(0); }
        __syncthreads();

        int buf = kt % NSTAGE;
        const __half* Ab = sA + buf * A_TILE_H;
        const __half* Bb = sB + buf * B_TILE_H;
#pragma unroll
        for (int ks = 0; ks < BK / 16; ks++) {
            int kk = ks * 16;
            uint32_t a[2][4], bb[8][2];
#pragma unroll
            for (int tm = 0; tm < 2; tm++) {
                int r = wm * 32 + tm * 16;
                a[tm][0] = *(const uint32_t*)(Ab + (r + g    ) * APADH + kk + 2*tg);
                a[tm][1] = *(const uint32_t*)(Ab + (r + g + 8) * APADH + kk + 2*tg);
                a[tm][2] = *(const uint32_t*)(Ab + (r + g    ) * APADH + kk + 8 + 2*tg);
                a[tm][3] = *(const uint32_t*)(Ab + (r + g + 8) * APADH + kk + 8 + 2*tg);
            }
#pragma unroll
            for (int nt = 0; nt < 8; nt++) {
                int c = wn * 64 + nt * 8 + g;
                bb[nt][0] = *(const uint32_t*)(Bb + c * BPADH + kk + 2*tg);
                bb[nt][1] = *(const uint32_t*)(Bb + c * BPADH + kk + 8 + 2*tg);
            }
#pragma unroll
            for (int tm = 0; tm < 2; tm++)
#pragma unroll
                for (int nt = 0; nt < 8; nt++)
                    mma_f16(acc[tm][nt], a[tm], bb[nt]);
        }
        __syncthreads();
    }

#pragma unroll
    for (int tm = 0; tm < 2; tm++) {
#pragma unroll
        for (int nt = 0; nt < 8; nt++) {
            int r = m0 + wm * 32 + tm * 16 + g;
            int c = wn * 64 + nt * 8 + tg * 2;
            float2 v0 = make_float2(softplus_f(acc[tm][nt][0]), softplus_f(acc[tm][nt][1]));
            float2 v1 = make_float2(softplus_f(acc[tm][nt][2]), softplus_f(acc[tm][nt][3]));
            *(float2*)&out[(size_t)r * OO + c]       = v0;
            *(float2*)&out[(size_t)(r + 8) * OO + c] = v1;
        }
    }
}

// ---------------- launch ----------------
extern "C" void kernel_launch(void* const* d_in, const int* in_sizes, int n_in,
                              void* d_out, int out_size) {
    const float* x      = (const float*)d_in[0];
    const float* adj    = (const float*)d_in[1];
    const float* gamma  = (const float*)d_in[2];
    const float* beta   = (const float*)d_in[3];
    const float* Wself  = (const float*)d_in[4];
    const float* Wneigh = (const float*)d_in[5];
    float* out = (float*)d_out;

    cudaFuncSetAttribute(gemm1_kernel, cudaFuncAttributeMaxDynamicSharedMemorySize, SMEM_BYTES);
    cudaFuncSetAttribute(gemm2_kernel, cudaFuncAttributeMaxDynamicSharedMemorySize, SMEM_BYTES);

    zero_cs_kernel<<<ROWS / 256, 256>>>();
    wtrans_kernel<<<dim3(FF / 32, OO / 32), 256>>>(Wself, Wneigh);
    degree_kernel<<<ROWS / 64, 256>>>(adj);
    ln_kernel<<<ROWS / 32, 256>>>(x, gamma, beta);
    gemm1_kernel<<<dim3(NN / BM, BATCH), NTH, SMEM_BYTES>>>();
    gemm2_kernel<<<ROWS / BM, NTH, SMEM_BYTES>>>(out);
}

// round 6
// speedup vs baseline: 2.9764x; 1.0505x over previous
#include <cuda_runtime.h>
#include <cuda_fp16.h>
#include <cstdint>
#include <math.h>

#define BATCH 8
#define NN    2048
#define FF    256
#define OO    256
#define ROWS  (BATCH*NN)   /* 16384 */

// GEMM tiling: 128x256 CTA tile, K-step 32, 512 threads, fp16, 4-stage cp.async
#define BM 128
#define BN 256
#define BK 32
#define NTH 512
#define APADH 40                 /* halfs per A smem row */
#define BPADH 40                 /* halfs per B smem row */
#define A_TILE_H (BM*APADH)      /* 5120 halfs  = 10240 B */
#define B_TILE_H (BN*BPADH)      /* 10240 halfs = 20480 B */
#define NSTAGE 4
#define SMEM_BYTES (NSTAGE*(A_TILE_H+B_TILE_H)*2)   /* 122880 B */

#define LN_SMEM (256*136*2)      /* 69632 B */

// ---------------- scratch ----------------
__device__ float  g_rs  [ROWS];
__device__ float  g_cs  [ROWS];
__device__ __half g_adjh[(size_t)BATCH*NN*NN];
__device__ __half g_xnh [ROWS*FF];
__device__ __half g_xshT[ROWS*FF];       // [b][f][n]
__device__ __half g_zh  [ROWS*FF];
__device__ __half g_wT  [2*FF*OO];       // [0]=(Ws+Wn)^T, [1]=Wn^T, [o][k]

// ---------------- helpers ----------------
__device__ __forceinline__ uint32_t h2u(__half2 h) {
    return *reinterpret_cast<uint32_t*>(&h);
}
__device__ __forceinline__ float softplus_f(float x) {
    return fmaxf(x, 0.0f) + log1pf(expf(-fabsf(x)));
}
__device__ __forceinline__ void cp16(uint32_t dst, const void* src) {
    asm volatile("cp.async.cg.shared.global [%0], [%1], 16;\n" :: "r"(dst), "l"(src));
}
#define CP_COMMIT() asm volatile("cp.async.commit_group;\n" ::: "memory")
#define CP_WAIT(n)  asm volatile("cp.async.wait_group %0;\n" :: "n"(n) : "memory")

__device__ __forceinline__ void mma_f16(float (&d)[4], const uint32_t (&a)[4], const uint32_t (&b)[2]) {
    asm volatile(
        "mma.sync.aligned.m16n8k16.row.col.f32.f16.f16.f32 "
        "{%0,%1,%2,%3}, {%4,%5,%6,%7}, {%8,%9}, {%0,%1,%2,%3};\n"
        : "+f"(d[0]), "+f"(d[1]), "+f"(d[2]), "+f"(d[3])
        : "r"(a[0]), "r"(a[1]), "r"(a[2]), "r"(a[3]), "r"(b[0]), "r"(b[1]));
}
__device__ __forceinline__ void ldsm4(uint32_t (&r)[4], uint32_t addr) {
    asm volatile("ldmatrix.sync.aligned.m8n8.x4.shared.b16 {%0,%1,%2,%3}, [%4];"
                 : "=r"(r[0]), "=r"(r[1]), "=r"(r[2]), "=r"(r[3]) : "r"(addr));
}

// ---------------- tiny prep kernels ----------------
__global__ void zero_cs_kernel() {
    g_cs[blockIdx.x * 256 + threadIdx.x] = 0.f;
}

__global__ void __launch_bounds__(256) wtrans_kernel(const float* __restrict__ Ws,
                                                     const float* __restrict__ Wn) {
    __shared__ float t1[32][33], t2[32][33];
    int tx = threadIdx.x & 31, ty = threadIdx.x >> 5;
    int k0 = blockIdx.x * 32, o0 = blockIdx.y * 32;
#pragma unroll
    for (int i = 0; i < 4; i++) {
        int k = k0 + ty + i * 8;
        float wn = Wn[(size_t)k * OO + o0 + tx];
        float ws = Ws[(size_t)k * OO + o0 + tx];
        t1[ty + i * 8][tx] = ws + wn;
        t2[ty + i * 8][tx] = wn;
    }
    __syncthreads();
#pragma unroll
    for (int i = 0; i < 4; i++) {
        int o = o0 + ty + i * 8;
        g_wT[(size_t)o * FF + k0 + tx]           = __float2half_rn(t1[tx][ty + i * 8]);
        g_wT[FF * OO + (size_t)o * FF + k0 + tx] = __float2half_rn(t2[tx][ty + i * 8]);
    }
}

// ---------------- fused degree + fp16-convert: one adj pass ----------------
__global__ void __launch_bounds__(256) degree_kernel(const float* __restrict__ adj) {
    __shared__ float rowpart[64][9];
    int tid = threadIdx.x, lane = tid & 31, w = tid >> 5;
    size_t r0 = (size_t)blockIdx.x * 64;
    const float* base = adj + r0 * NN;
    int c0 = tid * 4;

    float cs[8] = {0,0,0,0,0,0,0,0};
#pragma unroll 4
    for (int rr = 0; rr < 64; rr++) {
        float4 v0 = *(const float4*)(base + (size_t)rr * NN + c0);
        float4 v1 = *(const float4*)(base + (size_t)rr * NN + c0 + 1024);
        __half2 h0 = __floats2half2_rn(v0.x, v0.y);
        __half2 h1 = __floats2half2_rn(v0.z, v0.w);
        __half2 h2 = __floats2half2_rn(v1.x, v1.y);
        __half2 h3 = __floats2half2_rn(v1.z, v1.w);
        __half* hd = g_adjh + (r0 + rr) * NN;
        *(uint2*)(hd + c0)        = make_uint2(h2u(h0), h2u(h1));
        *(uint2*)(hd + c0 + 1024) = make_uint2(h2u(h2), h2u(h3));

        cs[0] += v0.x; cs[1] += v0.y; cs[2] += v0.z; cs[3] += v0.w;
        cs[4] += v1.x; cs[5] += v1.y; cs[6] += v1.z; cs[7] += v1.w;
        float rs = v0.x + v0.y + v0.z + v0.w + v1.x + v1.y + v1.z + v1.w;
#pragma unroll
        for (int off = 16; off > 0; off >>= 1) rs += __shfl_xor_sync(0xffffffffu, rs, off);
        if (lane == 0) rowpart[rr][w] = rs;
    }
    __syncthreads();
    if (tid < 64) {
        float s = 0.f;
#pragma unroll
        for (int j = 0; j < 8; j++) s += rowpart[tid][j];
        g_rs[r0 + tid] = s;
    }
    int b = (int)(r0 >> 11);
    float* cbase = g_cs + (size_t)b * NN;
#pragma unroll
    for (int j = 0; j < 4; j++) atomicAdd(cbase + c0 + j, cs[j]);
#pragma unroll
    for (int j = 0; j < 4; j++) atomicAdd(cbase + c0 + 1024 + j, cs[4 + j]);
}

// ---------------- layernorm: 128 rows/block, coalesced transposed writes ----------------
__global__ void __launch_bounds__(256) ln_kernel(const float* __restrict__ x,
                                                 const float* __restrict__ gamma,
                                                 const float* __restrict__ beta) {
    extern __shared__ __half tr[];   // [256 features][136]
    int tid = threadIdx.x, w = tid >> 5, lane = tid & 31;
    size_t r0 = (size_t)blockIdx.x * 128;
    int b  = (int)(r0 >> 11);
    int k0 = (int)(r0 & 2047);

    const float4* pg = (const float4*)gamma;
    const float4* pb = (const float4*)beta;
    float4 g0 = pg[lane], g1 = pg[lane + 32];
    float4 b0 = pb[lane], b1 = pb[lane + 32];
    float gm[8], bt[8];
    gm[0]=g0.x; gm[1]=g0.y; gm[2]=g0.z; gm[3]=g0.w; gm[4]=g1.x; gm[5]=g1.y; gm[6]=g1.z; gm[7]=g1.w;
    bt[0]=b0.x; bt[1]=b0.y; bt[2]=b0.z; bt[3]=b0.w; bt[4]=b1.x; bt[5]=b1.y; bt[6]=b1.z; bt[7]=b1.w;

#pragma unroll 4
    for (int s = 0; s < 16; s++) {
        int kk = w * 16 + s;
        size_t row = r0 + kk;
        const float4* px = (const float4*)(x + row * FF);
        float4 v0 = px[lane], v1 = px[lane + 32];

        float sm = v0.x + v0.y + v0.z + v0.w + v1.x + v1.y + v1.z + v1.w;
        float sq = v0.x*v0.x + v0.y*v0.y + v0.z*v0.z + v0.w*v0.w
                 + v1.x*v1.x + v1.y*v1.y + v1.z*v1.z + v1.w*v1.w;
#pragma unroll
        for (int off = 16; off > 0; off >>= 1) {
            sm += __shfl_xor_sync(0xffffffffu, sm, off);
            sq += __shfl_xor_sync(0xffffffffu, sq, off);
        }
        float mu   = sm * (1.0f / FF);
        float var  = sq * (1.0f / FF) - mu * mu;
        float rstd = rsqrtf(var + 1e-5f);
        float din  = g_rs[row];
        float sinv = (din != 0.f) ? rsqrtf(din) : 0.f;

        float xv[8], xn[8];
        xv[0]=v0.x; xv[1]=v0.y; xv[2]=v0.z; xv[3]=v0.w; xv[4]=v1.x; xv[5]=v1.y; xv[6]=v1.z; xv[7]=v1.w;
#pragma unroll
        for (int j = 0; j < 8; j++) {
            xn[j] = (xv[j] - mu) * rstd * gm[j] + bt[j];
            int n = (j < 4) ? (lane * 4 + j) : (128 + lane * 4 + j - 4);
            tr[n * 136 + kk] = __float2half_rn(sinv * xn[j]);
        }
        __half2 p0 = __floats2half2_rn(xn[0], xn[1]);
        __half2 p1 = __floats2half2_rn(xn[2], xn[3]);
        __half2 p2 = __floats2half2_rn(xn[4], xn[5]);
        __half2 p3 = __floats2half2_rn(xn[6], xn[7]);
        __half* dst = g_xnh + row * FF;
        *(uint2*)(dst + lane * 4)       = make_uint2(h2u(p0), h2u(p1));
        *(uint2*)(dst + 128 + lane * 4) = make_uint2(h2u(p2), h2u(p3));
    }
    __syncthreads();

    // coalesced transposed write: 16 threads per feature row (16x16B = 256B segments)
    int f0 = tid >> 4;          // feature offset within a 16-group
    int c  = tid & 15;          // 16B chunk index
#pragma unroll
    for (int pass = 0; pass < 16; pass++) {
        int f = pass * 16 + f0;
        uint4 v = *(const uint4*)&tr[f * 136 + c * 8];
        *(uint4*)(g_xshT + (size_t)b * FF * NN + (size_t)f * NN + k0 + c * 8) = v;
    }
}

// ---------------- shared GEMM compute core (ldmatrix + mma) ----------------
struct Frag {
    uint32_t aoff, boff;   // per-lane ldmatrix byte offsets (within a buffer)
};

__device__ __forceinline__ void gemm_tile(float (&acc)[2][8][4],
                                          uint32_t Abase, uint32_t Bbase,
                                          const Frag& fr) {
#pragma unroll
    for (int ks = 0; ks < 2; ks++) {
        uint32_t kb = ks * 32;   // 16 halfs = 32 bytes
        uint32_t a[2][4], bp[4][4];
        ldsm4(a[0], Abase + fr.aoff + kb);
        ldsm4(a[1], Abase + fr.aoff + 16 * APADH * 2 + kb);
#pragma unroll
        for (int p = 0; p < 4; p++)
            ldsm4(bp[p], Bbase + fr.boff + p * 16 * BPADH * 2 + kb);
#pragma unroll
        for (int tm = 0; tm < 2; tm++)
#pragma unroll
            for (int nt = 0; nt < 8; nt++) {
                uint32_t bb[2] = { bp[nt >> 1][nt & 1], bp[nt >> 1][2 + (nt & 1)] };
                mma_f16(acc[tm][nt], a[tm], bb);
            }
    }
}

// ---------------- GEMM1: g_zh[b] = -s_out * (adjh[b] @ xs[b]) ----------------
__global__ void __launch_bounds__(NTH, 1) gemm1_kernel() {
    extern __shared__ __half sh[];
    uint32_t sAu = (uint32_t)__cvta_generic_to_shared(sh);
    uint32_t sBu = sAu + NSTAGE * A_TILE_H * 2;

    int b  = blockIdx.y;
    int m0 = blockIdx.x * BM;
    const __half* A  = g_adjh + (size_t)(b * NN + m0) * NN;
    const __half* Bt = g_xshT + (size_t)b * FF * NN;

    int tid = threadIdx.x, warp = tid >> 5, lane = tid & 31;
    int wm = warp >> 2, wn = warp & 3;
    int g = lane >> 2, tg = lane & 3;

    Frag fr;
    fr.aoff = ((wm * 32 + (lane & 15)) * APADH) * 2 + (lane >> 4) * 16;
    fr.boff = ((wn * 64 + (lane & 15)) * BPADH) * 2 + (lane >> 4) * 16;

    float acc[2][8][4];
#pragma unroll
    for (int i = 0; i < 2; i++)
#pragma unroll
        for (int j = 0; j < 8; j++)
#pragma unroll
            for (int k = 0; k < 4; k++) acc[i][j][k] = 0.f;

    auto load = [&](int kt, int buf) {
        int k0 = kt * BK;
        uint32_t Ad = sAu + buf * A_TILE_H * 2;
        uint32_t Bd = sBu + buf * B_TILE_H * 2;
        {
            int ar = tid >> 2, ac8 = (tid & 3) * 8;
            cp16(Ad + (ar * APADH + ac8) * 2, A + (size_t)ar * NN + k0 + ac8);
        }
#pragma unroll
        for (int l = 0; l < 2; l++) {
            int idx = tid + l * NTH;
            int br = idx >> 2, bc8 = (idx & 3) * 8;
            cp16(Bd + (br * BPADH + bc8) * 2, Bt + (size_t)br * NN + k0 + bc8);
        }
    };

    const int KT = NN / BK;   // 64
    load(0, 0); CP_COMMIT();
    load(1, 1); CP_COMMIT();
    load(2, 2); CP_COMMIT();

    for (int kt = 0; kt < KT; kt++) {
        CP_WAIT(2);
        __syncthreads();
        if (kt + 3 < KT) load(kt + 3, (kt + 3) & 3);
        CP_COMMIT();
        int buf = kt & 3;
        gemm_tile(acc, sAu + buf * A_TILE_H * 2, sBu + buf * B_TILE_H * 2, fr);
    }

    const float* cb = g_cs + (size_t)b * NN;
#pragma unroll
    for (int tm = 0; tm < 2; tm++) {
        int rl = m0 + wm * 32 + tm * 16 + g;
        float c0v = cb[rl], c1v = cb[rl + 8];
        float sc0 = (c0v != 0.f) ? -rsqrtf(c0v) : 0.f;
        float sc1 = (c1v != 0.f) ? -rsqrtf(c1v) : 0.f;
        __half* z0 = g_zh + ((size_t)b * NN + rl)     * FF;
        __half* z1 = g_zh + ((size_t)b * NN + rl + 8) * FF;
#pragma unroll
        for (int nt = 0; nt < 8; nt++) {
            int c = wn * 64 + nt * 8 + tg * 2;
            *(uint32_t*)(z0 + c) = h2u(__floats2half2_rn(acc[tm][nt][0]*sc0, acc[tm][nt][1]*sc0));
            *(uint32_t*)(z1 + c) = h2u(__floats2half2_rn(acc[tm][nt][2]*sc1, acc[tm][nt][3]*sc1));
        }
    }
}

// ---------------- GEMM2: out = softplus([xn|z] @ [Wsum;Wn]) ----------------
__global__ void __launch_bounds__(NTH, 1) gemm2_kernel(float* __restrict__ out) {
    extern __shared__ __half sh[];
    uint32_t sAu = (uint32_t)__cvta_generic_to_shared(sh);
    uint32_t sBu = sAu + NSTAGE * A_TILE_H * 2;

    int m0 = blockIdx.x * BM;
    int tid = threadIdx.x, warp = tid >> 5, lane = tid & 31;
    int wm = warp >> 2, wn = warp & 3;
    int g = lane >> 2, tg = lane & 3;

    Frag fr;
    fr.aoff = ((wm * 32 + (lane & 15)) * APADH) * 2 + (lane >> 4) * 16;
    fr.boff = ((wn * 64 + (lane & 15)) * BPADH) * 2 + (lane >> 4) * 16;

    float acc[2][8][4];
#pragma unroll
    for (int i = 0; i < 2; i++)
#pragma unroll
        for (int j = 0; j < 8; j++)
#pragma unroll
            for (int k = 0; k < 4; k++) acc[i][j][k] = 0.f;

    auto load = [&](int kt, int buf) {
        int kk0 = kt * BK;
        const __half* Asrc = (kk0 < FF) ? g_xnh : g_zh;
        const __half* Bsrc = g_wT + ((kk0 < FF) ? 0 : FF * OO);
        int kc = (kk0 < FF) ? kk0 : (kk0 - FF);
        uint32_t Ad = sAu + buf * A_TILE_H * 2;
        uint32_t Bd = sBu + buf * B_TILE_H * 2;
        {
            int ar = tid >> 2, ac8 = (tid & 3) * 8;
            cp16(Ad + (ar * APADH + ac8) * 2, Asrc + (size_t)(m0 + ar) * FF + kc + ac8);
        }
#pragma unroll
        for (int l = 0; l < 2; l++) {
            int idx = tid + l * NTH;
            int br = idx >> 2, bc8 = (idx & 3) * 8;
            cp16(Bd + (br * BPADH + bc8) * 2, Bsrc + (size_t)br * FF + kc + bc8);
        }
    };

    const int KT = (2 * FF) / BK;   // 16
    load(0, 0); CP_COMMIT();
    load(1, 1); CP_COMMIT();
    load(2, 2); CP_COMMIT();

    for (int kt = 0; kt < KT; kt++) {
        CP_WAIT(2);
        __syncthreads();
        if (kt + 3 < KT) load(kt + 3, (kt + 3) & 3);
        CP_COMMIT();
        int buf = kt & 3;
        gemm_tile(acc, sAu + buf * A_TILE_H * 2, sBu + buf * B_TILE_H * 2, fr);
    }

#pragma unroll
    for (int tm = 0; tm < 2; tm++) {
#pragma unroll
        for (int nt = 0; nt < 8; nt++) {
            int r = m0 + wm * 32 + tm * 16 + g;
            int c = wn * 64 + nt * 8 + tg * 2;
            float2 v0 = make_float2(softplus_f(acc[tm][nt][0]), softplus_f(acc[tm][nt][1]));
            float2 v1 = make_float2(softplus_f(acc[tm][nt][2]), softplus_f(acc[tm][nt][3]));
            *(float2*)&out[(size_t)r * OO + c]       = v0;
            *(float2*)&out[(size_t)(r + 8) * OO + c] = v1;
        }
    }
}

// ---------------- launch ----------------
extern "C" void kernel_launch(void* const* d_in, const int* in_sizes, int n_in,
                              void* d_out, int out_size) {
    const float* x      = (const float*)d_in[0];
    const float* adj    = (const float*)d_in[1];
    const float* gamma  = (const float*)d_in[2];
    const float* beta   = (const float*)d_in[3];
    const float* Wself  = (const float*)d_in[4];
    const float* Wneigh = (const float*)d_in[5];
    float* out = (float*)d_out;

    cudaFuncSetAttribute(gemm1_kernel, cudaFuncAttributeMaxDynamicSharedMemorySize, SMEM_BYTES);
    cudaFuncSetAttribute(gemm2_kernel, cudaFuncAttributeMaxDynamicSharedMemorySize, SMEM_BYTES);
    cudaFuncSetAttribute(ln_kernel,    cudaFuncAttributeMaxDynamicSharedMemorySize, LN_SMEM);

    zero_cs_kernel<<<ROWS / 256, 256>>>();
    wtrans_kernel<<<dim3(FF / 32, OO / 32), 256>>>(Wself, Wneigh);
    degree_kernel<<<ROWS / 64, 256>>>(adj);
    ln_kernel<<<ROWS / 128, 256, LN_SMEM>>>(x, gamma, beta);
    gemm1_kernel<<<dim3(NN / BM, BATCH), NTH, SMEM_BYTES>>>();
    gemm2_kernel<<<ROWS / BM, NTH, SMEM_BYTES>>>(out);
}

// round 7
// speedup vs baseline: 3.2048x; 1.0767x over previous
#include <cuda_runtime.h>
#include <cuda_fp16.h>
#include <cstdint>
#include <math.h>

#define BATCH 8
#define NN    2048
#define FF    256
#define OO    256
#define ROWS  (BATCH*NN)   /* 16384 */

// GEMM tiling: 128x256 CTA tile, K-step 64, 512 threads, fp16, 3-stage cp.async
#define BM 128
#define BN 256
#define BK 64
#define NTH 512
#define APADH 72                 /* halfs per A smem row (64 + 8 pad) */
#define BPADH 72                 /* halfs per B smem row */
#define A_TILE_H (BM*APADH)      /* 9216 halfs  = 18432 B */
#define B_TILE_H (BN*BPADH)      /* 18432 halfs = 36864 B */
#define NSTAGE 3
#define SMEM_BYTES (NSTAGE*(A_TILE_H+B_TILE_H)*2)   /* 165888 B */

// ---------------- scratch ----------------
__device__ float  g_rs  [ROWS];
__device__ float  g_cs  [ROWS];
__device__ __half g_adjh[(size_t)BATCH*NN*NN];
__device__ __half g_xnh [ROWS*FF];
__device__ __half g_xshT[ROWS*FF];       // [b][f][n]
__device__ __half g_zh  [ROWS*FF];
__device__ __half g_wT  [2*FF*OO];       // [0]=(Ws+Wn)^T, [1]=Wn^T, [o][k]

// ---------------- helpers ----------------
__device__ __forceinline__ uint32_t h2u(__half2 h) {
    return *reinterpret_cast<uint32_t*>(&h);
}
__device__ __forceinline__ float softplus_f(float x) {
    return fmaxf(x, 0.0f) + log1pf(expf(-fabsf(x)));
}
__device__ __forceinline__ void cp16(uint32_t dst, const void* src) {
    asm volatile("cp.async.cg.shared.global [%0], [%1], 16;\n" :: "r"(dst), "l"(src));
}
#define CP_COMMIT() asm volatile("cp.async.commit_group;\n" ::: "memory")
#define CP_WAIT(n)  asm volatile("cp.async.wait_group %0;\n" :: "n"(n) : "memory")

__device__ __forceinline__ void mma_f16(float (&d)[4], const uint32_t (&a)[4], const uint32_t (&b)[2]) {
    asm volatile(
        "mma.sync.aligned.m16n8k16.row.col.f32.f16.f16.f32 "
        "{%0,%1,%2,%3}, {%4,%5,%6,%7}, {%8,%9}, {%0,%1,%2,%3};\n"
        : "+f"(d[0]), "+f"(d[1]), "+f"(d[2]), "+f"(d[3])
        : "r"(a[0]), "r"(a[1]), "r"(a[2]), "r"(a[3]), "r"(b[0]), "r"(b[1]));
}
__device__ __forceinline__ void ldsm4(uint32_t (&r)[4], uint32_t addr) {
    asm volatile("ldmatrix.sync.aligned.m8n8.x4.shared.b16 {%0,%1,%2,%3}, [%4];"
                 : "=r"(r[0]), "=r"(r[1]), "=r"(r[2]), "=r"(r[3]) : "r"(addr));
}

// ---------------- tiny prep kernels ----------------
__global__ void zero_cs_kernel() {
    g_cs[blockIdx.x * 256 + threadIdx.x] = 0.f;
}

__global__ void __launch_bounds__(256) wtrans_kernel(const float* __restrict__ Ws,
                                                     const float* __restrict__ Wn) {
    __shared__ float t1[32][33], t2[32][33];
    int tx = threadIdx.x & 31, ty = threadIdx.x >> 5;
    int k0 = blockIdx.x * 32, o0 = blockIdx.y * 32;
#pragma unroll
    for (int i = 0; i < 4; i++) {
        int k = k0 + ty + i * 8;
        float wn = Wn[(size_t)k * OO + o0 + tx];
        float ws = Ws[(size_t)k * OO + o0 + tx];
        t1[ty + i * 8][tx] = ws + wn;
        t2[ty + i * 8][tx] = wn;
    }
    __syncthreads();
#pragma unroll
    for (int i = 0; i < 4; i++) {
        int o = o0 + ty + i * 8;
        g_wT[(size_t)o * FF + k0 + tx]           = __float2half_rn(t1[tx][ty + i * 8]);
        g_wT[FF * OO + (size_t)o * FF + k0 + tx] = __float2half_rn(t2[tx][ty + i * 8]);
    }
}

// ---------------- fused degree + fp16-convert: one adj pass ----------------
__global__ void __launch_bounds__(256) degree_kernel(const float* __restrict__ adj) {
    __shared__ float rowpart[64][9];
    int tid = threadIdx.x, lane = tid & 31, w = tid >> 5;
    size_t r0 = (size_t)blockIdx.x * 64;
    const float* base = adj + r0 * NN;
    int c0 = tid * 4;

    float cs[8] = {0,0,0,0,0,0,0,0};
#pragma unroll 4
    for (int rr = 0; rr < 64; rr++) {
        float4 v0 = *(const float4*)(base + (size_t)rr * NN + c0);
        float4 v1 = *(const float4*)(base + (size_t)rr * NN + c0 + 1024);
        __half2 h0 = __floats2half2_rn(v0.x, v0.y);
        __half2 h1 = __floats2half2_rn(v0.z, v0.w);
        __half2 h2 = __floats2half2_rn(v1.x, v1.y);
        __half2 h3 = __floats2half2_rn(v1.z, v1.w);
        __half* hd = g_adjh + (r0 + rr) * NN;
        *(uint2*)(hd + c0)        = make_uint2(h2u(h0), h2u(h1));
        *(uint2*)(hd + c0 + 1024) = make_uint2(h2u(h2), h2u(h3));

        cs[0] += v0.x; cs[1] += v0.y; cs[2] += v0.z; cs[3] += v0.w;
        cs[4] += v1.x; cs[5] += v1.y; cs[6] += v1.z; cs[7] += v1.w;
        float rs = v0.x + v0.y + v0.z + v0.w + v1.x + v1.y + v1.z + v1.w;
#pragma unroll
        for (int off = 16; off > 0; off >>= 1) rs += __shfl_xor_sync(0xffffffffu, rs, off);
        if (lane == 0) rowpart[rr][w] = rs;
    }
    __syncthreads();
    if (tid < 64) {
        float s = 0.f;
#pragma unroll
        for (int j = 0; j < 8; j++) s += rowpart[tid][j];
        g_rs[r0 + tid] = s;
    }
    int b = (int)(r0 >> 11);
    float* cbase = g_cs + (size_t)b * NN;
#pragma unroll
    for (int j = 0; j < 4; j++) atomicAdd(cbase + c0 + j, cs[j]);
#pragma unroll
    for (int j = 0; j < 4; j++) atomicAdd(cbase + c0 + 1024 + j, cs[4 + j]);
}

// ---------------- layernorm (round-5 design: 32 rows/block, 512 blocks) ----------------
__global__ void __launch_bounds__(256) ln_kernel(const float* __restrict__ x,
                                                 const float* __restrict__ gamma,
                                                 const float* __restrict__ beta) {
    __shared__ float tr[256 * 37];   // [feature][klocal]
    int tid = threadIdx.x, w = tid >> 5, lane = tid & 31;
    size_t r0 = (size_t)blockIdx.x * 32;
    int b  = (int)(r0 >> 11);
    int k0 = (int)(r0 & 2047);

    const float4* pg = (const float4*)gamma;
    const float4* pb = (const float4*)beta;
    float4 g0 = pg[lane], g1 = pg[lane + 32];
    float4 b0 = pb[lane], b1 = pb[lane + 32];

#pragma unroll
    for (int s = 0; s < 4; s++) {
        int kk = w * 4 + s;
        size_t row = r0 + kk;
        const float4* px = (const float4*)(x + row * FF);
        float4 v0 = px[lane], v1 = px[lane + 32];

        float sm = v0.x + v0.y + v0.z + v0.w + v1.x + v1.y + v1.z + v1.w;
        float sq = v0.x*v0.x + v0.y*v0.y + v0.z*v0.z + v0.w*v0.w
                 + v1.x*v1.x + v1.y*v1.y + v1.z*v1.z + v1.w*v1.w;
#pragma unroll
        for (int off = 16; off > 0; off >>= 1) {
            sm += __shfl_xor_sync(0xffffffffu, sm, off);
            sq += __shfl_xor_sync(0xffffffffu, sq, off);
        }
        float mu   = sm * (1.0f / FF);
        float var  = sq * (1.0f / FF) - mu * mu;
        float rstd = rsqrtf(var + 1e-5f);
        float din  = g_rs[row];
        float sinv = (din != 0.f) ? rsqrtf(din) : 0.f;

        float xv[8], gm[8], bt[8], xn[8];
        xv[0]=v0.x; xv[1]=v0.y; xv[2]=v0.z; xv[3]=v0.w; xv[4]=v1.x; xv[5]=v1.y; xv[6]=v1.z; xv[7]=v1.w;
        gm[0]=g0.x; gm[1]=g0.y; gm[2]=g0.z; gm[3]=g0.w; gm[4]=g1.x; gm[5]=g1.y; gm[6]=g1.z; gm[7]=g1.w;
        bt[0]=b0.x; bt[1]=b0.y; bt[2]=b0.z; bt[3]=b0.w; bt[4]=b1.x; bt[5]=b1.y; bt[6]=b1.z; bt[7]=b1.w;

#pragma unroll
        for (int j = 0; j < 8; j++) {
            xn[j] = (xv[j] - mu) * rstd * gm[j] + bt[j];
            int n = (j < 4) ? (lane * 4 + j) : (128 + lane * 4 + j - 4);
            tr[n * 37 + kk] = sinv * xn[j];
        }
        __half2 p0 = __floats2half2_rn(xn[0], xn[1]);
        __half2 p1 = __floats2half2_rn(xn[2], xn[3]);
        __half2 p2 = __floats2half2_rn(xn[4], xn[5]);
        __half2 p3 = __floats2half2_rn(xn[6], xn[7]);
        __half* dst = g_xnh + row * FF;
        *(uint2*)(dst + lane * 4)       = make_uint2(h2u(p0), h2u(p1));
        *(uint2*)(dst + 128 + lane * 4) = make_uint2(h2u(p2), h2u(p3));
    }
    __syncthreads();

    __half* dst = g_xshT + (size_t)b * FF * NN + (size_t)tid * NN + k0;
#pragma unroll
    for (int j = 0; j < 32; j += 8) {
        uint4 o;
        o.x = h2u(__floats2half2_rn(tr[tid*37 + j + 0], tr[tid*37 + j + 1]));
        o.y = h2u(__floats2half2_rn(tr[tid*37 + j + 2], tr[tid*37 + j + 3]));
        o.z = h2u(__floats2half2_rn(tr[tid*37 + j + 4], tr[tid*37 + j + 5]));
        o.w = h2u(__floats2half2_rn(tr[tid*37 + j + 6], tr[tid*37 + j + 7]));
        *(uint4*)(dst + j) = o;
    }
}

// ---------------- shared GEMM compute core (ldmatrix + mma, BK=64) ----------------
struct Frag {
    uint32_t aoff, boff;
};

__device__ __forceinline__ void gemm_tile(float (&acc)[2][8][4],
                                          uint32_t Abase, uint32_t Bbase,
                                          const Frag& fr) {
#pragma unroll
    for (int ks = 0; ks < 4; ks++) {
        uint32_t kb = ks * 32;   // 16 halfs = 32 bytes per step
        uint32_t a[2][4], bp[4][4];
        ldsm4(a[0], Abase + fr.aoff + kb);
        ldsm4(a[1], Abase + fr.aoff + 16 * APADH * 2 + kb);
#pragma unroll
        for (int p = 0; p < 4; p++)
            ldsm4(bp[p], Bbase + fr.boff + p * 16 * BPADH * 2 + kb);
#pragma unroll
        for (int tm = 0; tm < 2; tm++)
#pragma unroll
            for (int nt = 0; nt < 8; nt++) {
                uint32_t bb[2] = { bp[nt >> 1][nt & 1], bp[nt >> 1][2 + (nt & 1)] };
                mma_f16(acc[tm][nt], a[tm], bb);
            }
    }
}

// ---------------- GEMM1: g_zh[b] = -s_out * (adjh[b] @ xs[b]) ----------------
__global__ void __launch_bounds__(NTH, 1) gemm1_kernel() {
    extern __shared__ __half sh[];
    uint32_t sAu = (uint32_t)__cvta_generic_to_shared(sh);
    uint32_t sBu = sAu + NSTAGE * A_TILE_H * 2;

    int b  = blockIdx.y;
    int m0 = blockIdx.x * BM;
    const __half* A  = g_adjh + (size_t)(b * NN + m0) * NN;
    const __half* Bt = g_xshT + (size_t)b * FF * NN;

    int tid = threadIdx.x, warp = tid >> 5, lane = tid & 31;
    int wm = warp >> 2, wn = warp & 3;
    int g = lane >> 2, tg = lane & 3;

    Frag fr;
    fr.aoff = ((wm * 32 + (lane & 15)) * APADH) * 2 + (lane >> 4) * 16;
    fr.boff = ((wn * 64 + (lane & 15)) * BPADH) * 2 + (lane >> 4) * 16;

    float acc[2][8][4];
#pragma unroll
    for (int i = 0; i < 2; i++)
#pragma unroll
        for (int j = 0; j < 8; j++)
#pragma unroll
            for (int k = 0; k < 4; k++) acc[i][j][k] = 0.f;

    auto load = [&](int kt, int buf) {
        int k0 = kt * BK;
        uint32_t Ad = sAu + buf * A_TILE_H * 2;
        uint32_t Bd = sBu + buf * B_TILE_H * 2;
#pragma unroll
        for (int l = 0; l < 2; l++) {    // A: 128 rows x 8 chunks
            int idx = tid + l * NTH;
            int ar = idx >> 3, ac8 = (idx & 7) * 8;
            cp16(Ad + (ar * APADH + ac8) * 2, A + (size_t)ar * NN + k0 + ac8);
        }
#pragma unroll
        for (int l = 0; l < 4; l++) {    // B: 256 rows x 8 chunks
            int idx = tid + l * NTH;
            int br = idx >> 3, bc8 = (idx & 7) * 8;
            cp16(Bd + (br * BPADH + bc8) * 2, Bt + (size_t)br * NN + k0 + bc8);
        }
    };

    const int KT = NN / BK;   // 32
    load(0, 0); CP_COMMIT();
    load(1, 1); CP_COMMIT();

    for (int kt = 0; kt < KT; kt++) {
        CP_WAIT(1);
        __syncthreads();
        if (kt + 2 < KT) load(kt + 2, (kt + 2) % NSTAGE);
        CP_COMMIT();
        int buf = kt % NSTAGE;
        gemm_tile(acc, sAu + buf * A_TILE_H * 2, sBu + buf * B_TILE_H * 2, fr);
    }

    const float* cb = g_cs + (size_t)b * NN;
#pragma unroll
    for (int tm = 0; tm < 2; tm++) {
        int rl = m0 + wm * 32 + tm * 16 + g;
        float c0v = cb[rl], c1v = cb[rl + 8];
        float sc0 = (c0v != 0.f) ? -rsqrtf(c0v) : 0.f;
        float sc1 = (c1v != 0.f) ? -rsqrtf(c1v) : 0.f;
        __half* z0 = g_zh + ((size_t)b * NN + rl)     * FF;
        __half* z1 = g_zh + ((size_t)b * NN + rl + 8) * FF;
#pragma unroll
        for (int nt = 0; nt < 8; nt++) {
            int c = wn * 64 + nt * 8 + tg * 2;
            *(uint32_t*)(z0 + c) = h2u(__floats2half2_rn(acc[tm][nt][0]*sc0, acc[tm][nt][1]*sc0));
            *(uint32_t*)(z1 + c) = h2u(__floats2half2_rn(acc[tm][nt][2]*sc1, acc[tm][nt][3]*sc1));
        }
    }
}

// ---------------- GEMM2: out = softplus([xn|z] @ [Wsum;Wn]) ----------------
__global__ void __launch_bounds__(NTH, 1) gemm2_kernel(float* __restrict__ out) {
    extern __shared__ __half sh[];
    uint32_t sAu = (uint32_t)__cvta_generic_to_shared(sh);
    uint32_t sBu = sAu + NSTAGE * A_TILE_H * 2;

    int m0 = blockIdx.x * BM;
    int tid = threadIdx.x, warp = tid >> 5, lane = tid & 31;
    int wm = warp >> 2, wn = warp & 3;
    int g = lane >> 2, tg = lane & 3;

    Frag fr;
    fr.aoff = ((wm * 32 + (lane & 15)) * APADH) * 2 + (lane >> 4) * 16;
    fr.boff = ((wn * 64 + (lane & 15)) * BPADH) * 2 + (lane >> 4) * 16;

    float acc[2][8][4];
#pragma unroll
    for (int i = 0; i < 2; i++)
#pragma unroll
        for (int j = 0; j < 8; j++)
#pragma unroll
            for (int k = 0; k < 4; k++) acc[i][j][k] = 0.f;

    auto load = [&](int kt, int buf) {
        int kk0 = kt * BK;
        const __half* Asrc = (kk0 < FF) ? g_xnh : g_zh;
        const __half* Bsrc = g_wT + ((kk0 < FF) ? 0 : FF * OO);
        int kc = (kk0 < FF) ? kk0 : (kk0 - FF);
        uint32_t Ad = sAu + buf * A_TILE_H * 2;
        uint32_t Bd = sBu + buf * B_TILE_H * 2;
#pragma unroll
        for (int l = 0; l < 2; l++) {
            int idx = tid + l * NTH;
            int ar = idx >> 3, ac8 = (idx & 7) * 8;
            cp16(Ad + (ar * APADH + ac8) * 2, Asrc + (size_t)(m0 + ar) * FF + kc + ac8);
        }
#pragma unroll
        for (int l = 0; l < 4; l++) {
            int idx = tid + l * NTH;
            int br = idx >> 3, bc8 = (idx & 7) * 8;
            cp16(Bd + (br * BPADH + bc8) * 2, Bsrc + (size_t)br * FF + kc + bc8);
        }
    };

    const int KT = (2 * FF) / BK;   // 8
    load(0, 0); CP_COMMIT();
    load(1, 1); CP_COMMIT();

    for (int kt = 0; kt < KT; kt++) {
        CP_WAIT(1);
        __syncthreads();
        if (kt + 2 < KT) load(kt + 2, (kt + 2) % NSTAGE);
        CP_COMMIT();
        int buf = kt % NSTAGE;
        gemm_tile(acc, sAu + buf * A_TILE_H * 2, sBu + buf * B_TILE_H * 2, fr);
    }

#pragma unroll
    for (int tm = 0; tm < 2; tm++) {
#pragma unroll
        for (int nt = 0; nt < 8; nt++) {
            int r = m0 + wm * 32 + tm * 16 + g;
            int c = wn * 64 + nt * 8 + tg * 2;
            float2 v0 = make_float2(softplus_f(acc[tm][nt][0]), softplus_f(acc[tm][nt][1]));
            float2 v1 = make_float2(softplus_f(acc[tm][nt][2]), softplus_f(acc[tm][nt][3]));
            *(float2*)&out[(size_t)r * OO + c]       = v0;
            *(float2*)&out[(size_t)(r + 8) * OO + c] = v1;
        }
    }
}

// ---------------- launch (gemm1 in profiler slot #4) ----------------
extern "C" void kernel_launch(void* const* d_in, const int* in_sizes, int n_in,
                              void* d_out, int out_size) {
    const float* x      = (const float*)d_in[0];
    const float* adj    = (const float*)d_in[1];
    const float* gamma  = (const float*)d_in[2];
    const float* beta   = (const float*)d_in[3];
    const float* Wself  = (const float*)d_in[4];
    const float* Wneigh = (const float*)d_in[5];
    float* out = (float*)d_out;

    cudaFuncSetAttribute(gemm1_kernel, cudaFuncAttributeMaxDynamicSharedMemorySize, SMEM_BYTES);
    cudaFuncSetAttribute(gemm2_kernel, cudaFuncAttributeMaxDynamicSharedMemorySize, SMEM_BYTES);

    zero_cs_kernel<<<ROWS / 256, 256>>>();
    degree_kernel<<<ROWS / 64, 256>>>(adj);
    ln_kernel<<<ROWS / 32, 256>>>(x, gamma, beta);
    gemm1_kernel<<<dim3(NN / BM, BATCH), NTH, SMEM_BYTES>>>();
    wtrans_kernel<<<dim3(FF / 32, OO / 32), 256>>>(Wself, Wneigh);
    gemm2_kernel<<<ROWS / BM, NTH, SMEM_BYTES>>>(out);
}

// round 9
// speedup vs baseline: 3.4361x; 1.0722x over previous
#include <cuda_runtime.h>
#include <cuda_fp16.h>
#include <cstdint>
#include <math.h>

#define BATCH 8
#define NN    2048
#define FF    256
#define OO    256
#define ROWS  (BATCH*NN)   /* 16384 */

// GEMM tiling: 128x128 CTA tile, K-step 64, 256 threads, fp16, 3-stage, 2 CTAs/SM
#define BM 128
#define BN 128
#define BK 64
#define NTH 256
#define APADH 72                 /* halfs per A smem row (64 + 8 pad) */
#define BPADH 72
#define A_TILE_H (BM*APADH)      /* 9216 halfs = 18432 B */
#define B_TILE_H (BN*BPADH)      /* 9216 halfs = 18432 B */
#define NSTAGE 3
#define SMEM_BYTES (NSTAGE*(A_TILE_H+B_TILE_H)*2)   /* 110592 B */

// ---------------- scratch ----------------
__device__ float  g_rs  [ROWS];
__device__ float  g_cs  [ROWS];
__device__ __half g_adjh[(size_t)BATCH*NN*NN];
__device__ __half g_xnh [ROWS*FF];
__device__ __half g_xshT[ROWS*FF];       // [b][f][n]
__device__ __half g_zh  [ROWS*FF];
__device__ __half g_wT  [2*FF*OO];       // [0]=(Ws+Wn)^T, [1]=Wn^T, [o][k]

// ---------------- helpers ----------------
__device__ __forceinline__ uint32_t h2u(__half2 h) {
    return *reinterpret_cast<uint32_t*>(&h);
}
__device__ __forceinline__ float softplus_f(float x) {
    return fmaxf(x, 0.0f) + log1pf(expf(-fabsf(x)));
}
__device__ __forceinline__ void cp16(uint32_t dst, const void* src) {
    asm volatile("cp.async.cg.shared.global [%0], [%1], 16;\n" :: "r"(dst), "l"(src));
}
#define CP_COMMIT() asm volatile("cp.async.commit_group;\n" ::: "memory")
#define CP_WAIT(n)  asm volatile("cp.async.wait_group %0;\n" :: "n"(n) : "memory")

__device__ __forceinline__ void mma_f16(float (&d)[4], const uint32_t (&a)[4], const uint32_t (&b)[2]) {
    asm volatile(
        "mma.sync.aligned.m16n8k16.row.col.f32.f16.f16.f32 "
        "{%0,%1,%2,%3}, {%4,%5,%6,%7}, {%8,%9}, {%0,%1,%2,%3};\n"
        : "+f"(d[0]), "+f"(d[1]), "+f"(d[2]), "+f"(d[3])
        : "r"(a[0]), "r"(a[1]), "r"(a[2]), "r"(a[3]), "r"(b[0]), "r"(b[1]));
}
__device__ __forceinline__ void ldsm4(uint32_t (&r)[4], uint32_t addr) {
    asm volatile("ldmatrix.sync.aligned.m8n8.x4.shared.b16 {%0,%1,%2,%3}, [%4];"
                 : "=r"(r[0]), "=r"(r[1]), "=r"(r[2]), "=r"(r[3]) : "r"(addr));
}

// ---------------- tiny prep kernels ----------------
__global__ void zero_cs_kernel() {
    g_cs[blockIdx.x * 256 + threadIdx.x] = 0.f;
}

__global__ void __launch_bounds__(256) wtrans_kernel(const float* __restrict__ Ws,
                                                     const float* __restrict__ Wn) {
    __shared__ float t1[32][33], t2[32][33];
    int tx = threadIdx.x & 31, ty = threadIdx.x >> 5;
    int k0 = blockIdx.x * 32, o0 = blockIdx.y * 32;
#pragma unroll
    for (int i = 0; i < 4; i++) {
        int k = k0 + ty + i * 8;
        float wn = Wn[(size_t)k * OO + o0 + tx];
        float ws = Ws[(size_t)k * OO + o0 + tx];
        t1[ty + i * 8][tx] = ws + wn;
        t2[ty + i * 8][tx] = wn;
    }
    __syncthreads();
#pragma unroll
    for (int i = 0; i < 4; i++) {
        int o = o0 + ty + i * 8;
        g_wT[(size_t)o * FF + k0 + tx]           = __float2half_rn(t1[tx][ty + i * 8]);
        g_wT[FF * OO + (size_t)o * FF + k0 + tx] = __float2half_rn(t2[tx][ty + i * 8]);
    }
}

// ---------------- fused degree + fp16-convert: one adj pass, 512 blocks ----------------
__global__ void __launch_bounds__(256) degree_kernel(const float* __restrict__ adj) {
    __shared__ float rowpart[32][9];
    int tid = threadIdx.x, lane = tid & 31, w = tid >> 5;
    size_t r0 = (size_t)blockIdx.x * 32;
    const float* base = adj + r0 * NN;
    int c0 = tid * 4;

    float cs[8] = {0,0,0,0,0,0,0,0};
#pragma unroll 8
    for (int rr = 0; rr < 32; rr++) {
        float4 v0 = *(const float4*)(base + (size_t)rr * NN + c0);
        float4 v1 = *(const float4*)(base + (size_t)rr * NN + c0 + 1024);
        __half2 h0 = __floats2half2_rn(v0.x, v0.y);
        __half2 h1 = __floats2half2_rn(v0.z, v0.w);
        __half2 h2 = __floats2half2_rn(v1.x, v1.y);
        __half2 h3 = __floats2half2_rn(v1.z, v1.w);
        __half* hd = g_adjh + (r0 + rr) * NN;
        *(uint2*)(hd + c0)        = make_uint2(h2u(h0), h2u(h1));
        *(uint2*)(hd + c0 + 1024) = make_uint2(h2u(h2), h2u(h3));

        cs[0] += v0.x; cs[1] += v0.y; cs[2] += v0.z; cs[3] += v0.w;
        cs[4] += v1.x; cs[5] += v1.y; cs[6] += v1.z; cs[7] += v1.w;
        float rs = v0.x + v0.y + v0.z + v0.w + v1.x + v1.y + v1.z + v1.w;
#pragma unroll
        for (int off = 16; off > 0; off >>= 1) rs += __shfl_xor_sync(0xffffffffu, rs, off);
        if (lane == 0) rowpart[rr][w] = rs;
    }
    __syncthreads();
    if (tid < 32) {
        float s = 0.f;
#pragma unroll
        for (int j = 0; j < 8; j++) s += rowpart[tid][j];
        g_rs[r0 + tid] = s;
    }
    int b = (int)(r0 >> 11);
    float* cbase = g_cs + (size_t)b * NN;
#pragma unroll
    for (int j = 0; j < 4; j++) atomicAdd(cbase + c0 + j, cs[j]);
#pragma unroll
    for (int j = 0; j < 4; j++) atomicAdd(cbase + c0 + 1024 + j, cs[4 + j]);
}

// ---------------- layernorm (32 rows/block, 512 blocks) ----------------
__global__ void __launch_bounds__(256) ln_kernel(const float* __restrict__ x,
                                                 const float* __restrict__ gamma,
                                                 const float* __restrict__ beta) {
    __shared__ float tr[256 * 37];
    int tid = threadIdx.x, w = tid >> 5, lane = tid & 31;
    size_t r0 = (size_t)blockIdx.x * 32;
    int b  = (int)(r0 >> 11);
    int k0 = (int)(r0 & 2047);

    const float4* pg = (const float4*)gamma;
    const float4* pb = (const float4*)beta;
    float4 g0 = pg[lane], g1 = pg[lane + 32];
    float4 b0 = pb[lane], b1 = pb[lane + 32];

#pragma unroll
    for (int s = 0; s < 4; s++) {
        int kk = w * 4 + s;
        size_t row = r0 + kk;
        const float4* px = (const float4*)(x + row * FF);
        float4 v0 = px[lane], v1 = px[lane + 32];

        float sm = v0.x + v0.y + v0.z + v0.w + v1.x + v1.y + v1.z + v1.w;
        float sq = v0.x*v0.x + v0.y*v0.y + v0.z*v0.z + v0.w*v0.w
                 + v1.x*v1.x + v1.y*v1.y + v1.z*v1.z + v1.w*v1.w;
#pragma unroll
        for (int off = 16; off > 0; off >>= 1) {
            sm += __shfl_xor_sync(0xffffffffu, sm, off);
            sq += __shfl_xor_sync(0xffffffffu, sq, off);
        }
        float mu   = sm * (1.0f / FF);
        float var  = sq * (1.0f / FF) - mu * mu;
        float rstd = rsqrtf(var + 1e-5f);
        float din  = g_rs[row];
        float sinv = (din != 0.f) ? rsqrtf(din) : 0.f;

        float xv[8], gm[8], bt[8], xn[8];
        xv[0]=v0.x; xv[1]=v0.y; xv[2]=v0.z; xv[3]=v0.w; xv[4]=v1.x; xv[5]=v1.y; xv[6]=v1.z; xv[7]=v1.w;
        gm[0]=g0.x; gm[1]=g0.y; gm[2]=g0.z; gm[3]=g0.w; gm[4]=g1.x; gm[5]=g1.y; gm[6]=g1.z; gm[7]=g1.w;
        bt[0]=b0.x; bt[1]=b0.y; bt[2]=b0.z; bt[3]=b0.w; bt[4]=b1.x; bt[5]=b1.y; bt[6]=b1.z; bt[7]=b1.w;

#pragma unroll
        for (int j = 0; j < 8; j++) {
            xn[j] = (xv[j] - mu) * rstd * gm[j] + bt[j];
            int n = (j < 4) ? (lane * 4 + j) : (128 + lane * 4 + j - 4);
            tr[n * 37 + kk] = sinv * xn[j];
        }
        __half2 p0 = __floats2half2_rn(xn[0], xn[1]);
        __half2 p1 = __floats2half2_rn(xn[2], xn[3]);
        __half2 p2 = __floats2half2_rn(xn[4], xn[5]);
        __half2 p3 = __floats2half2_rn(xn[6], xn[7]);
        __half* dst = g_xnh + row * FF;
        *(uint2*)(dst + lane * 4)       = make_uint2(h2u(p0), h2u(p1));
        *(uint2*)(dst + 128 + lane * 4) = make_uint2(h2u(p2), h2u(p3));
    }
    __syncthreads();

    __half* dst = g_xshT + (size_t)b * FF * NN + (size_t)tid * NN + k0;
#pragma unroll
    for (int j = 0; j < 32; j += 8) {
        uint4 o;
        o.x = h2u(__floats2half2_rn(tr[tid*37 + j + 0], tr[tid*37 + j + 1]));
        o.y = h2u(__floats2half2_rn(tr[tid*37 + j + 2], tr[tid*37 + j + 3]));
        o.z = h2u(__floats2half2_rn(tr[tid*37 + j + 4], tr[tid*37 + j + 5]));
        o.w = h2u(__floats2half2_rn(tr[tid*37 + j + 6], tr[tid*37 + j + 7]));
        *(uint4*)(dst + j) = o;
    }
}

// ---------------- GEMM compute core: 8 warps = 4(m) x 2(n), warp tile 32x64 ----------------
struct Frag {
    uint32_t aoff, boff;
};

__device__ __forceinline__ void gemm_tile(float (&acc)[2][8][4],
                                          uint32_t Abase, uint32_t Bbase,
                                          const Frag& fr) {
#pragma unroll
    for (int ks = 0; ks < 4; ks++) {
        uint32_t kb = ks * 32;
        uint32_t a[2][4], bp[4][4];
        ldsm4(a[0], Abase + fr.aoff + kb);
        ldsm4(a[1], Abase + fr.aoff + 16 * APADH * 2 + kb);
#pragma unroll
        for (int p = 0; p < 4; p++)
            ldsm4(bp[p], Bbase + fr.boff + p * 16 * BPADH * 2 + kb);
#pragma unroll
        for (int tm = 0; tm < 2; tm++)
#pragma unroll
            for (int nt = 0; nt < 8; nt++) {
                uint32_t bb[2] = { bp[nt >> 1][nt & 1], bp[nt >> 1][2 + (nt & 1)] };
                mma_f16(acc[tm][nt], a[tm], bb);
            }
    }
}

// ---------------- GEMM1: g_zh[b] = -s_out * (adjh[b] @ xs[b]) ----------------
__global__ void __launch_bounds__(NTH, 2) gemm1_kernel() {
    extern __shared__ __half sh[];
    uint32_t sAu = (uint32_t)__cvta_generic_to_shared(sh);
    uint32_t sBu = sAu + NSTAGE * A_TILE_H * 2;

    int b  = blockIdx.z;
    int m0 = blockIdx.x * BM;
    int n0 = blockIdx.y * BN;
    const __half* A  = g_adjh + (size_t)(b * NN + m0) * NN;
    const __half* Bt = g_xshT + (size_t)b * FF * NN + (size_t)n0 * NN;

    int tid = threadIdx.x, warp = tid >> 5, lane = tid & 31;
    int wm = warp >> 1, wn = warp & 1;
    int g = lane >> 2, tg = lane & 3;

    Frag fr;
    fr.aoff = ((wm * 32 + (lane & 15)) * APADH) * 2 + (lane >> 4) * 16;
    fr.boff = ((wn * 64 + (lane & 15)) * BPADH) * 2 + (lane >> 4) * 16;

    float acc[2][8][4];
#pragma unroll
    for (int i = 0; i < 2; i++)
#pragma unroll
        for (int j = 0; j < 8; j++)
#pragma unroll
            for (int k = 0; k < 4; k++) acc[i][j][k] = 0.f;

    auto load = [&](int kt, int buf) {
        int k0 = kt * BK;
        uint32_t Ad = sAu + buf * A_TILE_H * 2;
        uint32_t Bd = sBu + buf * B_TILE_H * 2;
#pragma unroll
        for (int l = 0; l < 4; l++) {    // A: 128 rows x 8 chunks of 16B
            int idx = tid + l * NTH;
            int ar = idx >> 3, ac8 = (idx & 7) * 8;
            cp16(Ad + (ar * APADH + ac8) * 2, A + (size_t)ar * NN + k0 + ac8);
        }
#pragma unroll
        for (int l = 0; l < 4; l++) {    // B: 128 feats x 8 chunks
            int idx = tid + l * NTH;
            int br = idx >> 3, bc8 = (idx & 7) * 8;
            cp16(Bd + (br * BPADH + bc8) * 2, Bt + (size_t)br * NN + k0 + bc8);
        }
    };

    const int KT = NN / BK;   // 32
    load(0, 0); CP_COMMIT();
    load(1, 1); CP_COMMIT();

    for (int kt = 0; kt < KT; kt++) {
        CP_WAIT(1);
        __syncthreads();
        if (kt + 2 < KT) load(kt + 2, (kt + 2) % NSTAGE);
        CP_COMMIT();
        int buf = kt % NSTAGE;
        gemm_tile(acc, sAu + buf * A_TILE_H * 2, sBu + buf * B_TILE_H * 2, fr);
    }

    const float* cb = g_cs + (size_t)b * NN;
#pragma unroll
    for (int tm = 0; tm < 2; tm++) {
        int rl = m0 + wm * 32 + tm * 16 + g;
        float c0v = cb[rl], c1v = cb[rl + 8];
        float sc0 = (c0v != 0.f) ? -rsqrtf(c0v) : 0.f;
        float sc1 = (c1v != 0.f) ? -rsqrtf(c1v) : 0.f;
        __half* z0 = g_zh + ((size_t)b * NN + rl)     * FF + n0;
        __half* z1 = g_zh + ((size_t)b * NN + rl + 8) * FF + n0;
#pragma unroll
        for (int nt = 0; nt < 8; nt++) {
            int c = wn * 64 + nt * 8 + tg * 2;
            *(uint32_t*)(z0 + c) = h2u(__floats2half2_rn(acc[tm][nt][0]*sc0, acc[tm][nt][1]*sc0));
            *(uint32_t*)(z1 + c) = h2u(__floats2half2_rn(acc[tm][nt][2]*sc1, acc[tm][nt][3]*sc1));
        }
    }
}

// ---------------- GEMM2: out = softplus([xn|z] @ [Wsum;Wn]) ----------------
__global__ void __launch_bounds__(NTH, 2) gemm2_kernel(float* __restrict__ out) {
    extern __shared__ __half sh[];
    uint32_t sAu = (uint32_t)__cvta_generic_to_shared(sh);
    uint32_t sBu = sAu + NSTAGE * A_TILE_H * 2;

    int m0 = blockIdx.x * BM;
    int n0 = blockIdx.y * BN;
    int tid = threadIdx.x, warp = tid >> 5, lane = tid & 31;
    int wm = warp >> 1, wn = warp & 1;
    int g = lane >> 2, tg = lane & 3;

    Frag fr;
    fr.aoff = ((wm * 32 + (lane & 15)) * APADH) * 2 + (lane >> 4) * 16;
    fr.boff = ((wn * 64 + (lane & 15)) * BPADH) * 2 + (lane >> 4) * 16;

    float acc[2][8][4];
#pragma unroll
    for (int i = 0; i < 2; i++)
#pragma unroll
        for (int j = 0; j < 8; j++)
#pragma unroll
            for (int k = 0; k < 4; k++) acc[i][j][k] = 0.f;

    auto load = [&](int kt, int buf) {
        int kk0 = kt * BK;
        const __half* Asrc = (kk0 < FF) ? g_xnh : g_zh;
        const __half* Bsrc = g_wT + ((kk0 < FF) ? 0 : FF * OO);
        int kc = (kk0 < FF) ? kk0 : (kk0 - FF);
        uint32_t Ad = sAu + buf * A_TILE_H * 2;
        uint32_t Bd = sBu + buf * B_TILE_H * 2;
#pragma unroll
        for (int l = 0; l < 4; l++) {
            int idx = tid + l * NTH;
            int ar = idx >> 3, ac8 = (idx & 7) * 8;
            cp16(Ad + (ar * APADH + ac8) * 2, Asrc + (size_t)(m0 + ar) * FF + kc + ac8);
        }
#pragma unroll
        for (int l = 0; l < 4; l++) {
            int idx = tid + l * NTH;
            int br = idx >> 3, bc8 = (idx & 7) * 8;
            cp16(Bd + (br * BPADH + bc8) * 2, Bsrc + (size_t)(n0 + br) * FF + kc + bc8);
        }
    };

    const int KT = (2 * FF) / BK;   // 8
    load(0, 0); CP_COMMIT();
    load(1, 1); CP_COMMIT();

    for (int kt = 0; kt < KT; kt++) {
        CP_WAIT(1);
        __syncthreads();
        if (kt + 2 < KT) load(kt + 2, (kt + 2) % NSTAGE);
        CP_COMMIT();
        int buf = kt % NSTAGE;
        gemm_tile(acc, sAu + buf * A_TILE_H * 2, sBu + buf * B_TILE_H * 2, fr);
    }

#pragma unroll
    for (int tm = 0; tm < 2; tm++) {
#pragma unroll
        for (int nt = 0; nt < 8; nt++) {
            int r = m0 + wm * 32 + tm * 16 + g;
            int c = n0 + wn * 64 + nt * 8 + tg * 2;
            float2 v0 = make_float2(softplus_f(acc[tm][nt][0]), softplus_f(acc[tm][nt][1]));
            float2 v1 = make_float2(softplus_f(acc[tm][nt][2]), softplus_f(acc[tm][nt][3]));
            *(float2*)&out[(size_t)r * OO + c]       = v0;
            *(float2*)&out[(size_t)(r + 8) * OO + c] = v1;
        }
    }
}

// ---------------- launch (gemm1 in profiler slot #4) ----------------
extern "C" void kernel_launch(void* const* d_in, const int* in_sizes, int n_in,
                              void* d_out, int out_size) {
    const float* x      = (const float*)d_in[0];
    const float* adj    = (const float*)d_in[1];
    const float* gamma  = (const float*)d_in[2];
    const float* beta   = (const float*)d_in[3];
    const float* Wself  = (const float*)d_in[4];
    const float* Wneigh = (const float*)d_in[5];
    float* out = (float*)d_out;

    cudaFuncSetAttribute(gemm1_kernel, cudaFuncAttributeMaxDynamicSharedMemorySize, SMEM_BYTES);
    cudaFuncSetAttribute(gemm2_kernel, cudaFuncAttributeMaxDynamicSharedMemorySize, SMEM_BYTES);

    zero_cs_kernel<<<ROWS / 256, 256>>>();
    degree_kernel<<<ROWS / 32, 256>>>(adj);
    ln_kernel<<<ROWS / 32, 256>>>(x, gamma, beta);
    gemm1_kernel<<<dim3(NN / BM, FF / BN, BATCH), NTH, SMEM_BYTES>>>();
    wtrans_kernel<<<dim3(FF / 32, OO / 32), 256>>>(Wself, Wneigh);
    gemm2_kernel<<<dim3(ROWS / BM, OO / BN), NTH, SMEM_BYTES>>>(out);
}